// round 4
// baseline (speedup 1.0000x reference)
#include <cuda_runtime.h>
#include <cstdint>
#include <cstddef>

// Problem-size capacities (fixed dataset: N=100000, E=3200000)
#define MAXN 100000
#define MAXE 3200000

// Scratch: __device__ globals (no allocation allowed)
__device__ float g_h1[MAXN * 64];     // layer1 features h = xW1  [N,8,8]
__device__ float g_as1[MAXN * 8];
__device__ float g_ad1[MAXN * 8];
__device__ float g_den1[MAXN * 8];
__device__ float g_acc1[MAXN * 64];   // layer1 aggregation, then elu'd -> layer2 input
__device__ float g_h2[MAXN * 128];    // layer2 features [N,8,16]
__device__ float g_as2[MAXN * 8];
__device__ float g_ad2[MAXN * 8];
__device__ float g_den2[MAXN * 8];
__device__ float g_acc2[MAXN * 128];

static inline int cdiv(int a, int b) { return (a + b - 1) / b; }

__device__ __forceinline__ void red_add_v4(float* p, float a, float b, float c, float d) {
    asm volatile("red.global.add.v4.f32 [%0], {%1,%2,%3,%4};"
                 :: "l"(p), "f"(a), "f"(b), "f"(c), "f"(d) : "memory");
}
__device__ __forceinline__ void red_add_v2(float* p, float a, float b) {
    asm volatile("red.global.add.v2.f32 [%0], {%1,%2};"
                 :: "l"(p), "f"(a), "f"(b) : "memory");
}

// ---------------------------------------------------------------------------
// GEMM1: C[N,64] = X[N,512] * W[512,64], fp32, tiled 64x64, K-chunks of 32
// ---------------------------------------------------------------------------
__global__ __launch_bounds__(256) void gemm1_kernel(
    const float* __restrict__ X, const float* __restrict__ W,
    float* __restrict__ H, int N)
{
    __shared__ float As[64][33];
    __shared__ float Bs[32][64];
    const int tid = threadIdx.x;
    const int tx = tid & 15;          // 16 col-groups of 4
    const int ty = tid >> 4;          // 16 row-groups of 4
    const int rowBase = blockIdx.x * 64;

    float acc[4][4];
#pragma unroll
    for (int i = 0; i < 4; i++)
#pragma unroll
        for (int j = 0; j < 4; j++) acc[i][j] = 0.f;

    for (int k0 = 0; k0 < 512; k0 += 32) {
        // A: 64 rows x 32 cols = 512 float4
#pragma unroll
        for (int i = tid; i < 512; i += 256) {
            int r = i >> 3, c4 = (i & 7) << 2;
            int row = rowBase + r;
            float4 v = make_float4(0.f, 0.f, 0.f, 0.f);
            if (row < N) v = *(const float4*)&X[(size_t)row * 512 + k0 + c4];
            As[r][c4] = v.x; As[r][c4 + 1] = v.y; As[r][c4 + 2] = v.z; As[r][c4 + 3] = v.w;
        }
        // B: 32 x 64 = 512 float4
#pragma unroll
        for (int i = tid; i < 512; i += 256) {
            int r = i >> 4, c4 = (i & 15) << 2;
            *(float4*)&Bs[r][c4] = *(const float4*)&W[(size_t)(k0 + r) * 64 + c4];
        }
        __syncthreads();
#pragma unroll
        for (int k = 0; k < 32; k++) {
            float a0 = As[ty * 4 + 0][k];
            float a1 = As[ty * 4 + 1][k];
            float a2 = As[ty * 4 + 2][k];
            float a3 = As[ty * 4 + 3][k];
            float4 b = *(float4*)&Bs[k][tx * 4];
            acc[0][0] += a0 * b.x; acc[0][1] += a0 * b.y; acc[0][2] += a0 * b.z; acc[0][3] += a0 * b.w;
            acc[1][0] += a1 * b.x; acc[1][1] += a1 * b.y; acc[1][2] += a1 * b.z; acc[1][3] += a1 * b.w;
            acc[2][0] += a2 * b.x; acc[2][1] += a2 * b.y; acc[2][2] += a2 * b.z; acc[2][3] += a2 * b.w;
            acc[3][0] += a3 * b.x; acc[3][1] += a3 * b.y; acc[3][2] += a3 * b.z; acc[3][3] += a3 * b.w;
        }
        __syncthreads();
    }
#pragma unroll
    for (int i = 0; i < 4; i++) {
        int row = rowBase + ty * 4 + i;
        if (row < N) {
            float4 v = make_float4(acc[i][0], acc[i][1], acc[i][2], acc[i][3]);
            *(float4*)&H[(size_t)row * 64 + tx * 4] = v;
        }
    }
}

// ---------------------------------------------------------------------------
// GEMM2: C[N,128] = X[N,64] * W[64,128], whole-K in smem, A transposed
// ---------------------------------------------------------------------------
__global__ __launch_bounds__(256) void gemm2_kernel(
    const float* __restrict__ X, const float* __restrict__ W,
    float* __restrict__ H, int N)
{
    __shared__ float As[64][64];   // [k][row]
    __shared__ float Bs[64][128];  // [k][col]   (total 48KB static)
    const int tid = threadIdx.x;
    const int tx = tid & 15;       // 16 col-groups of 8
    const int ty = tid >> 4;       // 16 row-groups of 4
    const int rowBase = blockIdx.x * 64;

    // B: 64 x 128 floats = 2048 float4
#pragma unroll
    for (int i = tid; i < 2048; i += 256) {
        int r = i >> 5, c4 = (i & 31) << 2;
        *(float4*)&Bs[r][c4] = *(const float4*)&W[(size_t)r * 128 + c4];
    }
    // A: 64 x 64 = 1024 float4, stored transposed
#pragma unroll
    for (int i = tid; i < 1024; i += 256) {
        int r = i >> 4, c4 = (i & 15) << 2;
        int row = rowBase + r;
        float4 v = make_float4(0.f, 0.f, 0.f, 0.f);
        if (row < N) v = *(const float4*)&X[(size_t)row * 64 + c4];
        As[c4 + 0][r] = v.x; As[c4 + 1][r] = v.y; As[c4 + 2][r] = v.z; As[c4 + 3][r] = v.w;
    }
    __syncthreads();

    float acc[4][8];
#pragma unroll
    for (int i = 0; i < 4; i++)
#pragma unroll
        for (int j = 0; j < 8; j++) acc[i][j] = 0.f;

#pragma unroll 8
    for (int k = 0; k < 64; k++) {
        float a0 = As[k][ty * 4 + 0];
        float a1 = As[k][ty * 4 + 1];
        float a2 = As[k][ty * 4 + 2];
        float a3 = As[k][ty * 4 + 3];
        float4 b0 = *(float4*)&Bs[k][tx * 8];
        float4 b1 = *(float4*)&Bs[k][tx * 8 + 4];
        acc[0][0] += a0 * b0.x; acc[0][1] += a0 * b0.y; acc[0][2] += a0 * b0.z; acc[0][3] += a0 * b0.w;
        acc[0][4] += a0 * b1.x; acc[0][5] += a0 * b1.y; acc[0][6] += a0 * b1.z; acc[0][7] += a0 * b1.w;
        acc[1][0] += a1 * b0.x; acc[1][1] += a1 * b0.y; acc[1][2] += a1 * b0.z; acc[1][3] += a1 * b0.w;
        acc[1][4] += a1 * b1.x; acc[1][5] += a1 * b1.y; acc[1][6] += a1 * b1.z; acc[1][7] += a1 * b1.w;
        acc[2][0] += a2 * b0.x; acc[2][1] += a2 * b0.y; acc[2][2] += a2 * b0.z; acc[2][3] += a2 * b0.w;
        acc[2][4] += a2 * b1.x; acc[2][5] += a2 * b1.y; acc[2][6] += a2 * b1.z; acc[2][7] += a2 * b1.w;
        acc[3][0] += a3 * b0.x; acc[3][1] += a3 * b0.y; acc[3][2] += a3 * b0.z; acc[3][3] += a3 * b0.w;
        acc[3][4] += a3 * b1.x; acc[3][5] += a3 * b1.y; acc[3][6] += a3 * b1.z; acc[3][7] += a3 * b1.w;
    }
#pragma unroll
    for (int i = 0; i < 4; i++) {
        int row = rowBase + ty * 4 + i;
        if (row < N) {
            *(float4*)&H[(size_t)row * 128 + tx * 8] =
                make_float4(acc[i][0], acc[i][1], acc[i][2], acc[i][3]);
            *(float4*)&H[(size_t)row * 128 + tx * 8 + 4] =
                make_float4(acc[i][4], acc[i][5], acc[i][6], acc[i][7]);
        }
    }
}

// ---------------------------------------------------------------------------
// Per-node attention coefficients: as[n,h] = sum_c h[n,h,c]*a_src[h,c], same for ad
// ---------------------------------------------------------------------------
template <int C>
__global__ __launch_bounds__(256) void alpha_kernel(
    const float* __restrict__ H, const float* __restrict__ a_s,
    const float* __restrict__ a_d, float* __restrict__ as_o,
    float* __restrict__ ad_o, int N)
{
    int i = blockIdx.x * blockDim.x + threadIdx.x;
    if (i >= N * 8) return;
    int n = i >> 3, h = i & 7;
    const float* hp = H + (size_t)n * 8 * C + h * C;
    float s = 0.f, d = 0.f;
#pragma unroll
    for (int c = 0; c < C; c++) {
        float v = __ldg(&hp[c]);
        s += v * __ldg(&a_s[h * C + c]);
        d += v * __ldg(&a_d[h * C + c]);
    }
    as_o[i] = s;
    ad_o[i] = d;
}

// ---------------------------------------------------------------------------
// Softmax denominators: den[d,h] += exp(leaky_relu(as[s,h]+ad[d,h]))
// (max-subtraction omitted: shift-invariant, values O(+-8) -> no overflow)
// ---------------------------------------------------------------------------
__global__ __launch_bounds__(256) void denom_kernel(
    const int* __restrict__ src, const int* __restrict__ dst,
    const float* __restrict__ as, const float* __restrict__ ad,
    float* __restrict__ den, int E, int N)
{
    int e = blockIdx.x * blockDim.x + threadIdx.x;
    if (e >= E + N) return;
    int s, d;
    if (e < E) { s = __ldg(&src[e]); d = __ldg(&dst[e]); }
    else       { s = e - E; d = s; }
    float4 s0 = __ldg((const float4*)&as[(size_t)s * 8]);
    float4 s1 = __ldg((const float4*)&as[(size_t)s * 8 + 4]);
    float4 d0 = __ldg((const float4*)&ad[(size_t)d * 8]);
    float4 d1 = __ldg((const float4*)&ad[(size_t)d * 8 + 4]);
    float v[8] = {s0.x + d0.x, s0.y + d0.y, s0.z + d0.z, s0.w + d0.w,
                  s1.x + d1.x, s1.y + d1.y, s1.z + d1.z, s1.w + d1.w};
#pragma unroll
    for (int h = 0; h < 8; h++) {
        float t = v[h];
        t = t > 0.f ? t : 0.2f * t;
        v[h] = __expf(t);
    }
    float* p = den + (size_t)d * 8;
    red_add_v4(p, v[0], v[1], v[2], v[3]);
    red_add_v4(p + 4, v[4], v[5], v[6], v[7]);
}

// ---------------------------------------------------------------------------
// Message scatter: acc[d, h*C+c] += alpha(e,h) * h[s, h*C+c].  One warp/edge.
// C=8 -> 64 ch, float2/lane.  C=16 -> 128 ch, float4/lane.
// ---------------------------------------------------------------------------
template <int C>
__global__ __launch_bounds__(256) void scatter_kernel(
    const int* __restrict__ src, const int* __restrict__ dst,
    const float* __restrict__ as, const float* __restrict__ ad,
    const float* __restrict__ den, const float* __restrict__ H,
    float* __restrict__ ACC, int E, int N)
{
    int gw = (blockIdx.x * blockDim.x + threadIdx.x) >> 5;
    int lane = threadIdx.x & 31;
    if (gw >= E + N) return;
    int s, d;
    if (gw < E) { s = __ldg(&src[gw]); d = __ldg(&dst[gw]); }
    else        { s = gw - E; d = s; }

    constexpr int HC = 8 * C;
    constexpr int V = HC / 32;     // 2 or 4
    int ch = lane * V;
    int h = ch / C;

    float ev = __ldg(&as[(size_t)s * 8 + h]) + __ldg(&ad[(size_t)d * 8 + h]);
    ev = ev > 0.f ? ev : 0.2f * ev;
    float alpha = __expf(ev) / __ldg(&den[(size_t)d * 8 + h]);

    const float* hp = H + (size_t)s * HC + ch;
    float* ap = ACC + (size_t)d * HC + ch;
    if (V == 4) {
        float4 v = __ldg((const float4*)hp);
        red_add_v4(ap, v.x * alpha, v.y * alpha, v.z * alpha, v.w * alpha);
    } else {
        float2 v = __ldg((const float2*)hp);
        red_add_v2(ap, v.x * alpha, v.y * alpha);
    }
}

// ---------------------------------------------------------------------------
// Finalize layer1: in-place  acc = elu(acc + b1[ch])
// ---------------------------------------------------------------------------
__global__ __launch_bounds__(256) void finalize1_kernel(
    float* __restrict__ acc, const float* __restrict__ b, int N)
{
    int i = blockIdx.x * blockDim.x + threadIdx.x;
    if (i >= N * 64) return;
    float v = acc[i] + __ldg(&b[i & 63]);
    acc[i] = v > 0.f ? v : (__expf(v) - 1.f);
}

// ---------------------------------------------------------------------------
// Finalize layer2: out[n,c] = mean_h acc[n,h*16+c] + b2[c]
// ---------------------------------------------------------------------------
__global__ __launch_bounds__(256) void finalize2_kernel(
    const float* __restrict__ acc, const float* __restrict__ b,
    float* __restrict__ out, int N)
{
    int i = blockIdx.x * blockDim.x + threadIdx.x;
    if (i >= N * 16) return;
    int n = i >> 4, c = i & 15;
    const float* p = acc + (size_t)n * 128 + c;
    float s = 0.f;
#pragma unroll
    for (int h = 0; h < 8; h++) s += p[h * 16];
    out[i] = s * 0.125f + __ldg(&b[c]);
}

// ---------------------------------------------------------------------------
extern "C" void kernel_launch(void* const* d_in, const int* in_sizes, int n_in,
                              void* d_out, int out_size)
{
    const float* x      = (const float*)d_in[0];
    const int*   ei     = (const int*)  d_in[1];
    const float* W1     = (const float*)d_in[2];
    const float* a_src1 = (const float*)d_in[3];
    const float* a_dst1 = (const float*)d_in[4];
    const float* b1     = (const float*)d_in[5];
    const float* W2     = (const float*)d_in[6];
    const float* a_src2 = (const float*)d_in[7];
    const float* a_dst2 = (const float*)d_in[8];
    const float* b2     = (const float*)d_in[9];

    const int N = in_sizes[0] / 512;
    const int E = in_sizes[1] / 2;
    const int ET = E + N;
    const int* src = ei;
    const int* dst = ei + E;

    float *h1, *as1, *ad1, *den1, *acc1, *h2, *as2, *ad2, *den2, *acc2;
    cudaGetSymbolAddress((void**)&h1,   g_h1);
    cudaGetSymbolAddress((void**)&as1,  g_as1);
    cudaGetSymbolAddress((void**)&ad1,  g_ad1);
    cudaGetSymbolAddress((void**)&den1, g_den1);
    cudaGetSymbolAddress((void**)&acc1, g_acc1);
    cudaGetSymbolAddress((void**)&h2,   g_h2);
    cudaGetSymbolAddress((void**)&as2,  g_as2);
    cudaGetSymbolAddress((void**)&ad2,  g_ad2);
    cudaGetSymbolAddress((void**)&den2, g_den2);
    cudaGetSymbolAddress((void**)&acc2, g_acc2);

    cudaMemsetAsync(den1, 0, (size_t)N * 8 * sizeof(float), 0);
    cudaMemsetAsync(acc1, 0, (size_t)N * 64 * sizeof(float), 0);
    cudaMemsetAsync(den2, 0, (size_t)N * 8 * sizeof(float), 0);
    cudaMemsetAsync(acc2, 0, (size_t)N * 128 * sizeof(float), 0);

    // ---- Layer 1 ----
    gemm1_kernel<<<cdiv(N, 64), 256>>>(x, W1, h1, N);
    alpha_kernel<8><<<cdiv(N * 8, 256), 256>>>(h1, a_src1, a_dst1, as1, ad1, N);
    denom_kernel<<<cdiv(ET, 256), 256>>>(src, dst, as1, ad1, den1, E, N);
    scatter_kernel<8><<<cdiv(ET * 32, 256), 256>>>(src, dst, as1, ad1, den1, h1, acc1, E, N);
    finalize1_kernel<<<cdiv(N * 64, 256), 256>>>(acc1, b1, N);

    // ---- Layer 2 ----
    gemm2_kernel<<<cdiv(N, 64), 256>>>(acc1, W2, h2, N);
    alpha_kernel<16><<<cdiv(N * 8, 256), 256>>>(h2, a_src2, a_dst2, as2, ad2, N);
    denom_kernel<<<cdiv(ET, 256), 256>>>(src, dst, as2, ad2, den2, E, N);
    scatter_kernel<16><<<cdiv(ET * 32, 256), 256>>>(src, dst, as2, ad2, den2, h2, acc2, E, N);
    finalize2_kernel<<<cdiv(N * 16, 256), 256>>>(acc2, b2, (float*)d_out, N);
}

// round 5
// speedup vs baseline: 1.2444x; 1.2444x over previous
#include <cuda_runtime.h>
#include <cstdint>
#include <cstddef>

// Problem-size capacities (fixed dataset: N=100000, E=3200000)
#define MAXN 100000
#define MAXE 3200000

// Scratch: __device__ globals (no allocation allowed)
__device__ float g_h1[MAXN * 64];     // layer1 features h = xW1  [N,8,8]
__device__ float g_as1[MAXN * 8];
__device__ float g_ad1[MAXN * 8];
__device__ float g_den1[MAXN * 8];
__device__ float g_acc1[MAXN * 64];   // layer1 aggregation, then elu'd -> layer2 input
__device__ float g_h2[MAXN * 128];    // layer2 features [N,8,16]
__device__ float g_as2[MAXN * 8];
__device__ float g_ad2[MAXN * 8];
__device__ float g_den2[MAXN * 8];
__device__ float g_acc2[MAXN * 128];

static inline int cdiv(int a, int b) { return (a + b - 1) / b; }

__device__ __forceinline__ void red_add_v4(float* p, float a, float b, float c, float d) {
    asm volatile("red.global.add.v4.f32 [%0], {%1,%2,%3,%4};"
                 :: "l"(p), "f"(a), "f"(b), "f"(c), "f"(d) : "memory");
}

// ---------------------------------------------------------------------------
// GEMM1: C[N,64] = X[N,512] * W[512,64], fp32, tiled 64x64, K-chunks of 32
// ---------------------------------------------------------------------------
__global__ __launch_bounds__(256) void gemm1_kernel(
    const float* __restrict__ X, const float* __restrict__ W,
    float* __restrict__ H, int N)
{
    __shared__ float As[64][33];
    __shared__ float Bs[32][64];
    const int tid = threadIdx.x;
    const int tx = tid & 15;          // 16 col-groups of 4
    const int ty = tid >> 4;          // 16 row-groups of 4
    const int rowBase = blockIdx.x * 64;

    float acc[4][4];
#pragma unroll
    for (int i = 0; i < 4; i++)
#pragma unroll
        for (int j = 0; j < 4; j++) acc[i][j] = 0.f;

    for (int k0 = 0; k0 < 512; k0 += 32) {
#pragma unroll
        for (int i = tid; i < 512; i += 256) {
            int r = i >> 3, c4 = (i & 7) << 2;
            int row = rowBase + r;
            float4 v = make_float4(0.f, 0.f, 0.f, 0.f);
            if (row < N) v = *(const float4*)&X[(size_t)row * 512 + k0 + c4];
            As[r][c4] = v.x; As[r][c4 + 1] = v.y; As[r][c4 + 2] = v.z; As[r][c4 + 3] = v.w;
        }
#pragma unroll
        for (int i = tid; i < 512; i += 256) {
            int r = i >> 4, c4 = (i & 15) << 2;
            *(float4*)&Bs[r][c4] = *(const float4*)&W[(size_t)(k0 + r) * 64 + c4];
        }
        __syncthreads();
#pragma unroll
        for (int k = 0; k < 32; k++) {
            float a0 = As[ty * 4 + 0][k];
            float a1 = As[ty * 4 + 1][k];
            float a2 = As[ty * 4 + 2][k];
            float a3 = As[ty * 4 + 3][k];
            float4 b = *(float4*)&Bs[k][tx * 4];
            acc[0][0] += a0 * b.x; acc[0][1] += a0 * b.y; acc[0][2] += a0 * b.z; acc[0][3] += a0 * b.w;
            acc[1][0] += a1 * b.x; acc[1][1] += a1 * b.y; acc[1][2] += a1 * b.z; acc[1][3] += a1 * b.w;
            acc[2][0] += a2 * b.x; acc[2][1] += a2 * b.y; acc[2][2] += a2 * b.z; acc[2][3] += a2 * b.w;
            acc[3][0] += a3 * b.x; acc[3][1] += a3 * b.y; acc[3][2] += a3 * b.z; acc[3][3] += a3 * b.w;
        }
        __syncthreads();
    }
#pragma unroll
    for (int i = 0; i < 4; i++) {
        int row = rowBase + ty * 4 + i;
        if (row < N) {
            float4 v = make_float4(acc[i][0], acc[i][1], acc[i][2], acc[i][3]);
            *(float4*)&H[(size_t)row * 64 + tx * 4] = v;
        }
    }
}

// ---------------------------------------------------------------------------
// GEMM2: C[N,128] = X[N,64] * W[64,128], whole-K in smem, A transposed
// ---------------------------------------------------------------------------
__global__ __launch_bounds__(256) void gemm2_kernel(
    const float* __restrict__ X, const float* __restrict__ W,
    float* __restrict__ H, int N)
{
    __shared__ float As[64][64];   // [k][row]
    __shared__ float Bs[64][128];  // [k][col]
    const int tid = threadIdx.x;
    const int tx = tid & 15;       // 16 col-groups of 8
    const int ty = tid >> 4;       // 16 row-groups of 4
    const int rowBase = blockIdx.x * 64;

#pragma unroll
    for (int i = tid; i < 2048; i += 256) {
        int r = i >> 5, c4 = (i & 31) << 2;
        *(float4*)&Bs[r][c4] = *(const float4*)&W[(size_t)r * 128 + c4];
    }
#pragma unroll
    for (int i = tid; i < 1024; i += 256) {
        int r = i >> 4, c4 = (i & 15) << 2;
        int row = rowBase + r;
        float4 v = make_float4(0.f, 0.f, 0.f, 0.f);
        if (row < N) v = *(const float4*)&X[(size_t)row * 64 + c4];
        As[c4 + 0][r] = v.x; As[c4 + 1][r] = v.y; As[c4 + 2][r] = v.z; As[c4 + 3][r] = v.w;
    }
    __syncthreads();

    float acc[4][8];
#pragma unroll
    for (int i = 0; i < 4; i++)
#pragma unroll
        for (int j = 0; j < 8; j++) acc[i][j] = 0.f;

#pragma unroll 8
    for (int k = 0; k < 64; k++) {
        float a0 = As[k][ty * 4 + 0];
        float a1 = As[k][ty * 4 + 1];
        float a2 = As[k][ty * 4 + 2];
        float a3 = As[k][ty * 4 + 3];
        float4 b0 = *(float4*)&Bs[k][tx * 8];
        float4 b1 = *(float4*)&Bs[k][tx * 8 + 4];
        acc[0][0] += a0 * b0.x; acc[0][1] += a0 * b0.y; acc[0][2] += a0 * b0.z; acc[0][3] += a0 * b0.w;
        acc[0][4] += a0 * b1.x; acc[0][5] += a0 * b1.y; acc[0][6] += a0 * b1.z; acc[0][7] += a0 * b1.w;
        acc[1][0] += a1 * b0.x; acc[1][1] += a1 * b0.y; acc[1][2] += a1 * b0.z; acc[1][3] += a1 * b0.w;
        acc[1][4] += a1 * b1.x; acc[1][5] += a1 * b1.y; acc[1][6] += a1 * b1.z; acc[1][7] += a1 * b1.w;
        acc[2][0] += a2 * b0.x; acc[2][1] += a2 * b0.y; acc[2][2] += a2 * b0.z; acc[2][3] += a2 * b0.w;
        acc[2][4] += a2 * b1.x; acc[2][5] += a2 * b1.y; acc[2][6] += a2 * b1.z; acc[2][7] += a2 * b1.w;
        acc[3][0] += a3 * b0.x; acc[3][1] += a3 * b0.y; acc[3][2] += a3 * b0.z; acc[3][3] += a3 * b0.w;
        acc[3][4] += a3 * b1.x; acc[3][5] += a3 * b1.y; acc[3][6] += a3 * b1.z; acc[3][7] += a3 * b1.w;
    }
#pragma unroll
    for (int i = 0; i < 4; i++) {
        int row = rowBase + ty * 4 + i;
        if (row < N) {
            *(float4*)&H[(size_t)row * 128 + tx * 8] =
                make_float4(acc[i][0], acc[i][1], acc[i][2], acc[i][3]);
            *(float4*)&H[(size_t)row * 128 + tx * 8 + 4] =
                make_float4(acc[i][4], acc[i][5], acc[i][6], acc[i][7]);
        }
    }
}

// ---------------------------------------------------------------------------
// Per-node attention coefficients: as[n,h] = sum_c h[n,h,c]*a_src[h,c]
// ---------------------------------------------------------------------------
template <int C>
__global__ __launch_bounds__(256) void alpha_kernel(
    const float* __restrict__ H, const float* __restrict__ a_s,
    const float* __restrict__ a_d, float* __restrict__ as_o,
    float* __restrict__ ad_o, int N)
{
    int i = blockIdx.x * blockDim.x + threadIdx.x;
    if (i >= N * 8) return;
    int n = i >> 3, h = i & 7;
    const float* hp = H + (size_t)n * 8 * C + h * C;
    float s = 0.f, d = 0.f;
#pragma unroll
    for (int c = 0; c < C; c++) {
        float v = __ldg(&hp[c]);
        s += v * __ldg(&a_s[h * C + c]);
        d += v * __ldg(&a_d[h * C + c]);
    }
    as_o[i] = s;
    ad_o[i] = d;
}

// ---------------------------------------------------------------------------
// Fused scatter, layer 1 (C=8, 64 ch): HALF-WARP (16 lanes) per edge.
//   acc[d, ch] += ex_h * h[s, ch]   (lane float4, red.v4)
//   den[d, h]  += ex_h              (2 lanes per edge, shuffled, red.v4)
// Softmax normalization (÷den) deferred to finalize — it factors out per (d,h).
// ---------------------------------------------------------------------------
__global__ __launch_bounds__(256) void scatter1_kernel(
    const int* __restrict__ src, const int* __restrict__ dst,
    const float* __restrict__ as, const float* __restrict__ ad,
    const float* __restrict__ H, float* __restrict__ ACC,
    float* __restrict__ DEN, int E, int ET)
{
    int gt = blockIdx.x * blockDim.x + threadIdx.x;
    int gw = gt >> 4;                    // edge id (half-warp granularity)
    bool valid = gw < ET;
    int gwc = valid ? gw : ET - 1;
    int lane16 = threadIdx.x & 15;
    int base = threadIdx.x & 16;         // half-warp base within warp (for shfl)

    int s, d;
    if (gwc < E) { s = __ldg(&src[gwc]); d = __ldg(&dst[gwc]); }
    else         { s = gwc - E; d = s; }

    int h = lane16 >> 1;
    float ev = __ldg(&as[(size_t)s * 8 + h]) + __ldg(&ad[(size_t)d * 8 + h]);
    ev = ev > 0.f ? ev : 0.2f * ev;
    float ex = __expf(ev);

    // Gather per-head ex values for den reduction (head h lives at lane16 = 2h)
    int off = (lane16 & 1) ? 8 : 0;      // lane16&1==0 -> heads 0..3, ==1 -> 4..7
    float e0 = __shfl_sync(0xffffffffu, ex, base + off + 0);
    float e1 = __shfl_sync(0xffffffffu, ex, base + off + 2);
    float e2 = __shfl_sync(0xffffffffu, ex, base + off + 4);
    float e3 = __shfl_sync(0xffffffffu, ex, base + off + 6);

    if (valid) {
        int ch = lane16 * 4;
        float4 v = __ldg((const float4*)&H[(size_t)s * 64 + ch]);
        red_add_v4(&ACC[(size_t)d * 64 + ch], v.x * ex, v.y * ex, v.z * ex, v.w * ex);
        if (lane16 < 2)
            red_add_v4(&DEN[(size_t)d * 8 + lane16 * 4], e0, e1, e2, e3);
    }
}

// ---------------------------------------------------------------------------
// Fused scatter, layer 2 (C=16, 128 ch): full warp per edge, float4/lane.
// ---------------------------------------------------------------------------
__global__ __launch_bounds__(256) void scatter2_kernel(
    const int* __restrict__ src, const int* __restrict__ dst,
    const float* __restrict__ as, const float* __restrict__ ad,
    const float* __restrict__ H, float* __restrict__ ACC,
    float* __restrict__ DEN, int E, int ET)
{
    int gw = (blockIdx.x * blockDim.x + threadIdx.x) >> 5;
    bool valid = gw < ET;
    int gwc = valid ? gw : ET - 1;
    int lane = threadIdx.x & 31;

    int s, d;
    if (gwc < E) { s = __ldg(&src[gwc]); d = __ldg(&dst[gwc]); }
    else         { s = gwc - E; d = s; }

    int h = lane >> 2;                   // head for this lane's float4 (16 ch/head)
    float ev = __ldg(&as[(size_t)s * 8 + h]) + __ldg(&ad[(size_t)d * 8 + h]);
    ev = ev > 0.f ? ev : 0.2f * ev;
    float ex = __expf(ev);

    // head h lives at lane 4h: lane0 -> heads 0..3 (lanes 0,4,8,12),
    // lane1 -> heads 4..7 (lanes 16,20,24,28)
    int off = (lane & 1) ? 16 : 0;
    float e0 = __shfl_sync(0xffffffffu, ex, off + 0);
    float e1 = __shfl_sync(0xffffffffu, ex, off + 4);
    float e2 = __shfl_sync(0xffffffffu, ex, off + 8);
    float e3 = __shfl_sync(0xffffffffu, ex, off + 12);

    if (valid) {
        int ch = lane * 4;
        float4 v = __ldg((const float4*)&H[(size_t)s * 128 + ch]);
        red_add_v4(&ACC[(size_t)d * 128 + ch], v.x * ex, v.y * ex, v.z * ex, v.w * ex);
        if (lane < 2)
            red_add_v4(&DEN[(size_t)d * 8 + lane * 4], e0, e1, e2, e3);
    }
}

// ---------------------------------------------------------------------------
// Finalize layer1: acc = elu(acc/den + b1)
// ---------------------------------------------------------------------------
__global__ __launch_bounds__(256) void finalize1_kernel(
    float* __restrict__ acc, const float* __restrict__ den,
    const float* __restrict__ b, int N)
{
    int i = blockIdx.x * blockDim.x + threadIdx.x;
    if (i >= N * 64) return;
    int n = i >> 6, ch = i & 63;
    float v = acc[i] / __ldg(&den[(size_t)n * 8 + (ch >> 3)]) + __ldg(&b[ch]);
    acc[i] = v > 0.f ? v : (__expf(v) - 1.f);
}

// ---------------------------------------------------------------------------
// Finalize layer2: out[n,c] = mean_h (acc[n,h*16+c]/den[n,h]) + b2[c]
// ---------------------------------------------------------------------------
__global__ __launch_bounds__(256) void finalize2_kernel(
    const float* __restrict__ acc, const float* __restrict__ den,
    const float* __restrict__ b, float* __restrict__ out, int N)
{
    int i = blockIdx.x * blockDim.x + threadIdx.x;
    if (i >= N * 16) return;
    int n = i >> 4, c = i & 15;
    const float* p = acc + (size_t)n * 128 + c;
    const float* dn = den + (size_t)n * 8;
    float s = 0.f;
#pragma unroll
    for (int h = 0; h < 8; h++) s += p[h * 16] / __ldg(&dn[h]);
    out[i] = s * 0.125f + __ldg(&b[c]);
}

// ---------------------------------------------------------------------------
extern "C" void kernel_launch(void* const* d_in, const int* in_sizes, int n_in,
                              void* d_out, int out_size)
{
    const float* x      = (const float*)d_in[0];
    const int*   ei     = (const int*)  d_in[1];
    const float* W1     = (const float*)d_in[2];
    const float* a_src1 = (const float*)d_in[3];
    const float* a_dst1 = (const float*)d_in[4];
    const float* b1     = (const float*)d_in[5];
    const float* W2     = (const float*)d_in[6];
    const float* a_src2 = (const float*)d_in[7];
    const float* a_dst2 = (const float*)d_in[8];
    const float* b2     = (const float*)d_in[9];

    const int N = in_sizes[0] / 512;
    const int E = in_sizes[1] / 2;
    const int ET = E + N;
    const int* src = ei;
    const int* dst = ei + E;

    float *h1, *as1, *ad1, *den1, *acc1, *h2, *as2, *ad2, *den2, *acc2;
    cudaGetSymbolAddress((void**)&h1,   g_h1);
    cudaGetSymbolAddress((void**)&as1,  g_as1);
    cudaGetSymbolAddress((void**)&ad1,  g_ad1);
    cudaGetSymbolAddress((void**)&den1, g_den1);
    cudaGetSymbolAddress((void**)&acc1, g_acc1);
    cudaGetSymbolAddress((void**)&h2,   g_h2);
    cudaGetSymbolAddress((void**)&as2,  g_as2);
    cudaGetSymbolAddress((void**)&ad2,  g_ad2);
    cudaGetSymbolAddress((void**)&den2, g_den2);
    cudaGetSymbolAddress((void**)&acc2, g_acc2);

    cudaMemsetAsync(den1, 0, (size_t)N * 8 * sizeof(float), 0);
    cudaMemsetAsync(acc1, 0, (size_t)N * 64 * sizeof(float), 0);
    cudaMemsetAsync(den2, 0, (size_t)N * 8 * sizeof(float), 0);
    cudaMemsetAsync(acc2, 0, (size_t)N * 128 * sizeof(float), 0);

    // ---- Layer 1 ----
    gemm1_kernel<<<cdiv(N, 64), 256>>>(x, W1, h1, N);
    alpha_kernel<8><<<cdiv(N * 8, 256), 256>>>(h1, a_src1, a_dst1, as1, ad1, N);
    scatter1_kernel<<<cdiv(ET * 16, 256), 256>>>(src, dst, as1, ad1, h1, acc1, den1, E, ET);
    finalize1_kernel<<<cdiv(N * 64, 256), 256>>>(acc1, den1, b1, N);

    // ---- Layer 2 ----
    gemm2_kernel<<<cdiv(N, 64), 256>>>(acc1, W2, h2, N);
    alpha_kernel<16><<<cdiv(N * 8, 256), 256>>>(h2, a_src2, a_dst2, as2, ad2, N);
    scatter2_kernel<<<cdiv(ET * 32, 256), 256>>>(src, dst, as2, ad2, h2, acc2, den2, E, ET);
    finalize2_kernel<<<cdiv(N * 16, 256), 256>>>(acc2, den2, b2, (float*)d_out, N);
}

// round 8
// speedup vs baseline: 2.3869x; 1.9181x over previous
#include <cuda_runtime.h>
#include <cstdint>
#include <cstddef>

// Problem-size capacities (fixed dataset: N=100000, E=3200000)
#define MAXN 100000
#define MAXE 3200000

// Scratch: __device__ globals (no allocation allowed)
__device__ float g_h1[MAXN * 64];     // layer1 features h = xW1  [N,8,8]
__device__ float g_as1[MAXN * 8];
__device__ float g_ad1[MAXN * 8];
__device__ float g_acc1[MAXN * 64];   // layer1 output (elu'd) -> layer2 input
__device__ float g_h2[MAXN * 128];    // layer2 features [N,8,16]
__device__ float g_as2[MAXN * 8];
__device__ float g_ad2[MAXN * 8];
// CSR scratch
__device__ int g_deg[MAXN];
__device__ int g_off[MAXN];
__device__ int g_cursor[MAXN];
__device__ int g_csr[MAXE];

static inline int cdiv(int a, int b) { return (a + b - 1) / b; }

// ---------------------------------------------------------------------------
// GEMM1: C[N,64] = X[N,512] * W[512,64], fp32, tile 128x64, K-chunks of 32.
// A stored k-major (transposed) in smem -> vectorized LDS.128 reads.
// ---------------------------------------------------------------------------
__global__ __launch_bounds__(256) void gemm1_kernel(
    const float* __restrict__ X, const float* __restrict__ W,
    float* __restrict__ H, int N)
{
    __shared__ float4 As4[32][33];   // [k][row/4], rows 128 -> 32 float4, +1 pad
    __shared__ float4 Bs4[32][16];   // [k][col/4], cols 64 -> 16 float4
    const int tid = threadIdx.x;
    const int tx = tid & 15;         // 16 col-groups of 4
    const int ty = tid >> 4;         // 16 row-groups of 8
    const int rowBase = blockIdx.x * 128;
    float* As = (float*)As4;         // scalar view, k-row stride = 132 floats

    float acc[8][4];
#pragma unroll
    for (int i = 0; i < 8; i++)
#pragma unroll
        for (int j = 0; j < 4; j++) acc[i][j] = 0.f;

    for (int k0 = 0; k0 < 512; k0 += 32) {
        // A: 128 rows x 32 cols = 1024 float4 loads, stored transposed [k][row]
#pragma unroll
        for (int i = tid; i < 1024; i += 256) {
            int r = i >> 3, c4 = (i & 7) << 2;
            int row = rowBase + r;
            float4 v = make_float4(0.f, 0.f, 0.f, 0.f);
            if (row < N) v = *(const float4*)&X[(size_t)row * 512 + k0 + c4];
            As[(c4 + 0) * 132 + r] = v.x;
            As[(c4 + 1) * 132 + r] = v.y;
            As[(c4 + 2) * 132 + r] = v.z;
            As[(c4 + 3) * 132 + r] = v.w;
        }
        // B: 32 x 64 floats = 512 float4
#pragma unroll
        for (int i = tid; i < 512; i += 256) {
            int r = i >> 4, c = i & 15;
            Bs4[r][c] = *(const float4*)&W[(size_t)(k0 + r) * 64 + c * 4];
        }
        __syncthreads();
#pragma unroll
        for (int k = 0; k < 32; k++) {
            float4 a0 = As4[k][ty * 2];
            float4 a1 = As4[k][ty * 2 + 1];
            float4 b  = Bs4[k][tx];
            acc[0][0] += a0.x * b.x; acc[0][1] += a0.x * b.y; acc[0][2] += a0.x * b.z; acc[0][3] += a0.x * b.w;
            acc[1][0] += a0.y * b.x; acc[1][1] += a0.y * b.y; acc[1][2] += a0.y * b.z; acc[1][3] += a0.y * b.w;
            acc[2][0] += a0.z * b.x; acc[2][1] += a0.z * b.y; acc[2][2] += a0.z * b.z; acc[2][3] += a0.z * b.w;
            acc[3][0] += a0.w * b.x; acc[3][1] += a0.w * b.y; acc[3][2] += a0.w * b.z; acc[3][3] += a0.w * b.w;
            acc[4][0] += a1.x * b.x; acc[4][1] += a1.x * b.y; acc[4][2] += a1.x * b.z; acc[4][3] += a1.x * b.w;
            acc[5][0] += a1.y * b.x; acc[5][1] += a1.y * b.y; acc[5][2] += a1.y * b.z; acc[5][3] += a1.y * b.w;
            acc[6][0] += a1.z * b.x; acc[6][1] += a1.z * b.y; acc[6][2] += a1.z * b.z; acc[6][3] += a1.z * b.w;
            acc[7][0] += a1.w * b.x; acc[7][1] += a1.w * b.y; acc[7][2] += a1.w * b.z; acc[7][3] += a1.w * b.w;
        }
        __syncthreads();
    }
#pragma unroll
    for (int i = 0; i < 8; i++) {
        int row = rowBase + ty * 8 + i;
        if (row < N) {
            *(float4*)&H[(size_t)row * 64 + tx * 4] =
                make_float4(acc[i][0], acc[i][1], acc[i][2], acc[i][3]);
        }
    }
}

// ---------------------------------------------------------------------------
// GEMM2: C[N,128] = X[N,64] * W[64,128], whole-K in smem, A transposed
// ---------------------------------------------------------------------------
__global__ __launch_bounds__(256) void gemm2_kernel(
    const float* __restrict__ X, const float* __restrict__ W,
    float* __restrict__ H, int N)
{
    __shared__ float As[64][64];   // [k][row]
    __shared__ float Bs[64][128];  // [k][col]
    const int tid = threadIdx.x;
    const int tx = tid & 15;       // 16 col-groups of 8
    const int ty = tid >> 4;       // 16 row-groups of 4
    const int rowBase = blockIdx.x * 64;

#pragma unroll
    for (int i = tid; i < 2048; i += 256) {
        int r = i >> 5, c4 = (i & 31) << 2;
        *(float4*)&Bs[r][c4] = *(const float4*)&W[(size_t)r * 128 + c4];
    }
#pragma unroll
    for (int i = tid; i < 1024; i += 256) {
        int r = i >> 4, c4 = (i & 15) << 2;
        int row = rowBase + r;
        float4 v = make_float4(0.f, 0.f, 0.f, 0.f);
        if (row < N) v = *(const float4*)&X[(size_t)row * 64 + c4];
        As[c4 + 0][r] = v.x; As[c4 + 1][r] = v.y; As[c4 + 2][r] = v.z; As[c4 + 3][r] = v.w;
    }
    __syncthreads();

    float acc[4][8];
#pragma unroll
    for (int i = 0; i < 4; i++)
#pragma unroll
        for (int j = 0; j < 8; j++) acc[i][j] = 0.f;

#pragma unroll 8
    for (int k = 0; k < 64; k++) {
        float a0 = As[k][ty * 4 + 0];
        float a1 = As[k][ty * 4 + 1];
        float a2 = As[k][ty * 4 + 2];
        float a3 = As[k][ty * 4 + 3];
        float4 b0 = *(float4*)&Bs[k][tx * 8];
        float4 b1 = *(float4*)&Bs[k][tx * 8 + 4];
        acc[0][0] += a0 * b0.x; acc[0][1] += a0 * b0.y; acc[0][2] += a0 * b0.z; acc[0][3] += a0 * b0.w;
        acc[0][4] += a0 * b1.x; acc[0][5] += a0 * b1.y; acc[0][6] += a0 * b1.z; acc[0][7] += a0 * b1.w;
        acc[1][0] += a1 * b0.x; acc[1][1] += a1 * b0.y; acc[1][2] += a1 * b0.z; acc[1][3] += a1 * b0.w;
        acc[1][4] += a1 * b1.x; acc[1][5] += a1 * b1.y; acc[1][6] += a1 * b1.z; acc[1][7] += a1 * b1.w;
        acc[2][0] += a2 * b0.x; acc[2][1] += a2 * b0.y; acc[2][2] += a2 * b0.z; acc[2][3] += a2 * b0.w;
        acc[2][4] += a2 * b1.x; acc[2][5] += a2 * b1.y; acc[2][6] += a2 * b1.z; acc[2][7] += a2 * b1.w;
        acc[3][0] += a3 * b0.x; acc[3][1] += a3 * b0.y; acc[3][2] += a3 * b0.z; acc[3][3] += a3 * b0.w;
        acc[3][4] += a3 * b1.x; acc[3][5] += a3 * b1.y; acc[3][6] += a3 * b1.z; acc[3][7] += a3 * b1.w;
    }
#pragma unroll
    for (int i = 0; i < 4; i++) {
        int row = rowBase + ty * 4 + i;
        if (row < N) {
            *(float4*)&H[(size_t)row * 128 + tx * 8] =
                make_float4(acc[i][0], acc[i][1], acc[i][2], acc[i][3]);
            *(float4*)&H[(size_t)row * 128 + tx * 8 + 4] =
                make_float4(acc[i][4], acc[i][5], acc[i][6], acc[i][7]);
        }
    }
}

// ---------------------------------------------------------------------------
// Per-node attention coefficients: as[n,h] = sum_c h[n,h,c]*a_src[h,c]
// ---------------------------------------------------------------------------
template <int C>
__global__ __launch_bounds__(256) void alpha_kernel(
    const float* __restrict__ H, const float* __restrict__ a_s,
    const float* __restrict__ a_d, float* __restrict__ as_o,
    float* __restrict__ ad_o, int N)
{
    int i = blockIdx.x * blockDim.x + threadIdx.x;
    if (i >= N * 8) return;
    int n = i >> 3, h = i & 7;
    const float* hp = H + (size_t)n * 8 * C + h * C;
    float s = 0.f, d = 0.f;
#pragma unroll
    for (int c = 0; c < C; c++) {
        float v = __ldg(&hp[c]);
        s += v * __ldg(&a_s[h * C + c]);
        d += v * __ldg(&a_d[h * C + c]);
    }
    as_o[i] = s;
    ad_o[i] = d;
}

// ---------------------------------------------------------------------------
// CSR build: histogram -> exclusive scan (3 kernels) -> fill
// ---------------------------------------------------------------------------
__global__ __launch_bounds__(256) void hist_kernel(
    const int* __restrict__ dst, int* __restrict__ deg, int E)
{
    int e = blockIdx.x * blockDim.x + threadIdx.x;
    if (e < E) atomicAdd(&deg[__ldg(&dst[e])], 1);
}

// Block-level exclusive scan: 1024 elems/block (4 per thread), 256 threads.
__global__ __launch_bounds__(256) void scan_partial_kernel(
    const int* __restrict__ deg, int* __restrict__ off,
    int* __restrict__ blockSums, int N)
{
    __shared__ int warpSums[8];
    int tid = threadIdx.x;
    int base = blockIdx.x * 1024 + tid * 4;
    int d0 = base + 0 < N ? deg[base + 0] : 0;
    int d1 = base + 1 < N ? deg[base + 1] : 0;
    int d2 = base + 2 < N ? deg[base + 2] : 0;
    int d3 = base + 3 < N ? deg[base + 3] : 0;
    int s = d0 + d1 + d2 + d3;

    int lane = tid & 31, wid = tid >> 5;
    int v = s;
#pragma unroll
    for (int o = 1; o < 32; o <<= 1) {
        int t = __shfl_up_sync(0xffffffffu, v, o);
        if (lane >= o) v += t;
    }
    if (lane == 31) warpSums[wid] = v;
    __syncthreads();
    if (wid == 0) {
        int w = lane < 8 ? warpSums[lane] : 0;
#pragma unroll
        for (int o = 1; o < 8; o <<= 1) {
            int t = __shfl_up_sync(0xffffffffu, w, o);
            if (lane >= o) w += t;
        }
        if (lane < 8) warpSums[lane] = w;
    }
    __syncthreads();
    int ex = v - s + (wid ? warpSums[wid - 1] : 0);
    if (base + 0 < N) off[base + 0] = ex;
    if (base + 1 < N) off[base + 1] = ex + d0;
    if (base + 2 < N) off[base + 2] = ex + d0 + d1;
    if (base + 3 < N) off[base + 3] = ex + d0 + d1 + d2;
    if (tid == 255) blockSums[blockIdx.x] = warpSums[7];
}

__global__ void scan_sums_kernel(int* __restrict__ blockSums, int nb)
{
    __shared__ int sm[1024];
    int t = threadIdx.x;
    for (int i = t; i < nb; i += blockDim.x) sm[i] = blockSums[i];
    __syncthreads();
    if (t == 0) {
        int run = 0;
        for (int i = 0; i < nb; i++) { int v = sm[i]; sm[i] = run; run += v; }
    }
    __syncthreads();
    for (int i = t; i < nb; i += blockDim.x) blockSums[i] = sm[i];
}

__global__ __launch_bounds__(256) void scan_add_kernel(
    int* __restrict__ off, const int* __restrict__ blockSums, int N)
{
    int i = blockIdx.x * blockDim.x + threadIdx.x;
    if (i < N) off[i] += __ldg(&blockSums[i >> 10]);
}

__global__ __launch_bounds__(256) void fill_kernel(
    const int* __restrict__ src, const int* __restrict__ dst,
    int* __restrict__ cursor, int* __restrict__ csr, int E)
{
    int e = blockIdx.x * blockDim.x + threadIdx.x;
    if (e >= E) return;
    int d = __ldg(&dst[e]);
    int pos = atomicAdd(&cursor[d], 1);
    csr[pos] = __ldg(&src[e]);
}

// ---------------------------------------------------------------------------
// Layer-1 aggregation (gather): warp per dst node. 64 ch, float2/lane.
// Fuses softmax normalization + bias + ELU. No atomics.
// ---------------------------------------------------------------------------
__global__ __launch_bounds__(256) void agg1_kernel(
    const int* __restrict__ csr, const int* __restrict__ off,
    const int* __restrict__ deg, const float* __restrict__ as,
    const float* __restrict__ ad, const float* __restrict__ H,
    const float* __restrict__ b, float* __restrict__ OUT, int N)
{
    int d = (blockIdx.x * blockDim.x + threadIdx.x) >> 5;
    if (d >= N) return;
    int lane = threadIdx.x & 31;
    int h = lane >> 2;          // 8 heads x 4 lanes, 2 ch per lane
    int c2 = lane * 2;

    float adh = __ldg(&ad[(size_t)d * 8 + h]);

    // self loop
    float ev = __ldg(&as[(size_t)d * 8 + h]) + adh;
    ev = ev > 0.f ? ev : 0.2f * ev;
    float ex = __expf(ev);
    float2 v = __ldg((const float2*)&H[(size_t)d * 64 + c2]);
    float ax = ex * v.x, ay = ex * v.y, den = ex;

    int beg = __ldg(&off[d]);
    int cnt = __ldg(&deg[d]);
#pragma unroll 2
    for (int j = 0; j < cnt; j++) {
        int s = __ldg(&csr[beg + j]);
        float e2 = __ldg(&as[(size_t)s * 8 + h]) + adh;
        e2 = e2 > 0.f ? e2 : 0.2f * e2;
        float x2 = __expf(e2);
        float2 u = __ldg((const float2*)&H[(size_t)s * 64 + c2]);
        ax += x2 * u.x; ay += x2 * u.y; den += x2;
    }
    float inv = 1.f / den;
    float o0 = ax * inv + __ldg(&b[c2]);
    float o1 = ay * inv + __ldg(&b[c2 + 1]);
    o0 = o0 > 0.f ? o0 : (__expf(o0) - 1.f);
    o1 = o1 > 0.f ? o1 : (__expf(o1) - 1.f);
    *(float2*)&OUT[(size_t)d * 64 + c2] = make_float2(o0, o1);
}

// ---------------------------------------------------------------------------
// Layer-2 aggregation (gather): warp per dst node. 128 ch, float4/lane.
// Fuses softmax normalization + head-mean + bias. Writes final output.
// ---------------------------------------------------------------------------
__global__ __launch_bounds__(256) void agg2_kernel(
    const int* __restrict__ csr, const int* __restrict__ off,
    const int* __restrict__ deg, const float* __restrict__ as,
    const float* __restrict__ ad, const float* __restrict__ H,
    const float* __restrict__ b, float* __restrict__ OUT, int N)
{
    int d = (blockIdx.x * blockDim.x + threadIdx.x) >> 5;
    if (d >= N) return;
    int lane = threadIdx.x & 31;
    int h = lane >> 2;          // 8 heads x 4 lanes, 4 ch per lane
    int c4 = lane * 4;

    float adh = __ldg(&ad[(size_t)d * 8 + h]);

    // self loop
    float ev = __ldg(&as[(size_t)d * 8 + h]) + adh;
    ev = ev > 0.f ? ev : 0.2f * ev;
    float ex = __expf(ev);
    float4 v = __ldg((const float4*)&H[(size_t)d * 128 + c4]);
    float a0 = ex * v.x, a1 = ex * v.y, a2 = ex * v.z, a3 = ex * v.w;
    float den = ex;

    int beg = __ldg(&off[d]);
    int cnt = __ldg(&deg[d]);
#pragma unroll 2
    for (int j = 0; j < cnt; j++) {
        int s = __ldg(&csr[beg + j]);
        float e2 = __ldg(&as[(size_t)s * 8 + h]) + adh;
        e2 = e2 > 0.f ? e2 : 0.2f * e2;
        float x2 = __expf(e2);
        float4 u = __ldg((const float4*)&H[(size_t)s * 128 + c4]);
        a0 += x2 * u.x; a1 += x2 * u.y; a2 += x2 * u.z; a3 += x2 * u.w;
        den += x2;
    }
    float inv = 1.f / den;
    a0 *= inv; a1 *= inv; a2 *= inv; a3 *= inv;

    // mean over heads: head index = bits [2:4] of lane -> butterfly over 4,8,16
#pragma unroll
    for (int o = 4; o <= 16; o <<= 1) {
        a0 += __shfl_xor_sync(0xffffffffu, a0, o);
        a1 += __shfl_xor_sync(0xffffffffu, a1, o);
        a2 += __shfl_xor_sync(0xffffffffu, a2, o);
        a3 += __shfl_xor_sync(0xffffffffu, a3, o);
    }
    if (lane < 4) {
        int c = lane * 4;
        float4 o4 = make_float4(
            a0 * 0.125f + __ldg(&b[c]),
            a1 * 0.125f + __ldg(&b[c + 1]),
            a2 * 0.125f + __ldg(&b[c + 2]),
            a3 * 0.125f + __ldg(&b[c + 3]));
        *(float4*)&OUT[(size_t)d * 16 + c] = o4;
    }
}

// ---------------------------------------------------------------------------
extern "C" void kernel_launch(void* const* d_in, const int* in_sizes, int n_in,
                              void* d_out, int out_size)
{
    const float* x      = (const float*)d_in[0];
    const int*   ei     = (const int*)  d_in[1];
    const float* W1     = (const float*)d_in[2];
    const float* a_src1 = (const float*)d_in[3];
    const float* a_dst1 = (const float*)d_in[4];
    const float* b1     = (const float*)d_in[5];
    const float* W2     = (const float*)d_in[6];
    const float* a_src2 = (const float*)d_in[7];
    const float* a_dst2 = (const float*)d_in[8];
    const float* b2     = (const float*)d_in[9];

    const int N = in_sizes[0] / 512;
    const int E = in_sizes[1] / 2;
    const int* src = ei;
    const int* dst = ei + E;

    float *h1, *as1, *ad1, *acc1, *h2, *as2, *ad2;
    int *deg, *off, *cursor, *csr;
    cudaGetSymbolAddress((void**)&h1,   g_h1);
    cudaGetSymbolAddress((void**)&as1,  g_as1);
    cudaGetSymbolAddress((void**)&ad1,  g_ad1);
    cudaGetSymbolAddress((void**)&acc1, g_acc1);
    cudaGetSymbolAddress((void**)&h2,   g_h2);
    cudaGetSymbolAddress((void**)&as2,  g_as2);
    cudaGetSymbolAddress((void**)&ad2,  g_ad2);
    cudaGetSymbolAddress((void**)&deg,    g_deg);
    cudaGetSymbolAddress((void**)&off,    g_off);
    cudaGetSymbolAddress((void**)&cursor, g_cursor);
    cudaGetSymbolAddress((void**)&csr,    g_csr);

    const int nb = cdiv(N, 1024);

    // ---- CSR build (overlaps conceptually with gemm1 on same stream order) ----
    cudaMemsetAsync(deg, 0, (size_t)N * sizeof(int), 0);
    hist_kernel<<<cdiv(E, 256), 256>>>(dst, deg, E);
    scan_partial_kernel<<<nb, 256>>>(deg, off, cursor /*reuse as blockSums? no*/, N);
    // NOTE: blockSums stored in cursor[0..nb) temporarily (nb ~ 98 << N)
    scan_sums_kernel<<<1, 256>>>(cursor, nb);
    scan_add_kernel<<<cdiv(N, 256), 256>>>(off, cursor, N);
    cudaMemcpyAsync(cursor, off, (size_t)N * sizeof(int),
                    cudaMemcpyDeviceToDevice, 0);
    fill_kernel<<<cdiv(E, 256), 256>>>(src, dst, cursor, csr, E);

    // ---- Layer 1 ----
    gemm1_kernel<<<cdiv(N, 128), 256>>>(x, W1, h1, N);
    alpha_kernel<8><<<cdiv(N * 8, 256), 256>>>(h1, a_src1, a_dst1, as1, ad1, N);
    agg1_kernel<<<cdiv(N * 32, 256), 256>>>(csr, off, deg, as1, ad1, h1, b1, acc1, N);

    // ---- Layer 2 ----
    gemm2_kernel<<<cdiv(N, 64), 256>>>(acc1, W2, h2, N);
    alpha_kernel<16><<<cdiv(N * 8, 256), 256>>>(h2, a_src2, a_dst2, as2, ad2, N);
    agg2_kernel<<<cdiv(N * 32, 256), 256>>>(csr, off, deg, as2, ad2, h2, b2, (float*)d_out, N);
}

// round 12
// speedup vs baseline: 2.4391x; 1.0219x over previous
#include <cuda_runtime.h>
#include <cstdint>
#include <cstddef>

// Problem-size capacities (fixed dataset: N=100000, E=3200000)
#define MAXN 100000
#define MAXE 3200000

// Scratch: __device__ globals (no allocation allowed)
__device__ float g_h1[MAXN * 64];     // layer1 features h = xW1  [N,8,8]
__device__ float g_as1[MAXN * 8];
__device__ float g_ad1[MAXN * 8];
__device__ float g_acc1[MAXN * 64];   // layer1 output (elu'd) -> layer2 input
__device__ float g_h2[MAXN * 128];    // layer2 features [N,8,16]
__device__ float g_as2[MAXN * 8];
__device__ float g_ad2[MAXN * 8];
// CSR scratch
__device__ int g_deg[MAXN];
__device__ int g_off[MAXN];
__device__ int g_cursor[MAXN];
__device__ int g_bsum[128];           // scan block sums (nb = ceil(N/1024) <= 98)
__device__ int g_csr[MAXE];

static inline int cdiv(int a, int b) { return (a + b - 1) / b; }

// Side stream + fork/join events, created once at static init (no device
// memory allocation involved — streams/events are driver objects).
static cudaStream_t g_s1;
static cudaEvent_t g_evFork, g_evJoin;
namespace {
struct StreamInit {
    StreamInit() {
        cudaStreamCreateWithFlags(&g_s1, cudaStreamNonBlocking);
        cudaEventCreateWithFlags(&g_evFork, cudaEventDisableTiming);
        cudaEventCreateWithFlags(&g_evJoin, cudaEventDisableTiming);
    }
} s_streamInit;
}

// ---------------------------------------------------------------------------
// GEMM1: C[N,64] = X[N,512] * W[512,64], fp32, tile 128x64, K-chunks of 32.
// A stored k-major (transposed) in smem -> vectorized LDS.128 reads.
// ---------------------------------------------------------------------------
__global__ __launch_bounds__(256) void gemm1_kernel(
    const float* __restrict__ X, const float* __restrict__ W,
    float* __restrict__ H, int N)
{
    __shared__ float4 As4[32][33];   // [k][row/4], rows 128 -> 32 float4, +1 pad
    __shared__ float4 Bs4[32][16];   // [k][col/4], cols 64 -> 16 float4
    const int tid = threadIdx.x;
    const int tx = tid & 15;         // 16 col-groups of 4
    const int ty = tid >> 4;         // 16 row-groups of 8
    const int rowBase = blockIdx.x * 128;
    float* As = (float*)As4;         // scalar view, k-row stride = 132 floats

    float acc[8][4];
#pragma unroll
    for (int i = 0; i < 8; i++)
#pragma unroll
        for (int j = 0; j < 4; j++) acc[i][j] = 0.f;

    for (int k0 = 0; k0 < 512; k0 += 32) {
        // A: 128 rows x 32 cols = 1024 float4 loads, stored transposed [k][row]
#pragma unroll
        for (int i = tid; i < 1024; i += 256) {
            int r = i >> 3, c4 = (i & 7) << 2;
            int row = rowBase + r;
            float4 v = make_float4(0.f, 0.f, 0.f, 0.f);
            if (row < N) v = *(const float4*)&X[(size_t)row * 512 + k0 + c4];
            As[(c4 + 0) * 132 + r] = v.x;
            As[(c4 + 1) * 132 + r] = v.y;
            As[(c4 + 2) * 132 + r] = v.z;
            As[(c4 + 3) * 132 + r] = v.w;
        }
        // B: 32 x 64 floats = 512 float4
#pragma unroll
        for (int i = tid; i < 512; i += 256) {
            int r = i >> 4, c = i & 15;
            Bs4[r][c] = *(const float4*)&W[(size_t)(k0 + r) * 64 + c * 4];
        }
        __syncthreads();
#pragma unroll
        for (int k = 0; k < 32; k++) {
            float4 a0 = As4[k][ty * 2];
            float4 a1 = As4[k][ty * 2 + 1];
            float4 b  = Bs4[k][tx];
            acc[0][0] += a0.x * b.x; acc[0][1] += a0.x * b.y; acc[0][2] += a0.x * b.z; acc[0][3] += a0.x * b.w;
            acc[1][0] += a0.y * b.x; acc[1][1] += a0.y * b.y; acc[1][2] += a0.y * b.z; acc[1][3] += a0.y * b.w;
            acc[2][0] += a0.z * b.x; acc[2][1] += a0.z * b.y; acc[2][2] += a0.z * b.z; acc[2][3] += a0.z * b.w;
            acc[3][0] += a0.w * b.x; acc[3][1] += a0.w * b.y; acc[3][2] += a0.w * b.z; acc[3][3] += a0.w * b.w;
            acc[4][0] += a1.x * b.x; acc[4][1] += a1.x * b.y; acc[4][2] += a1.x * b.z; acc[4][3] += a1.x * b.w;
            acc[5][0] += a1.y * b.x; acc[5][1] += a1.y * b.y; acc[5][2] += a1.y * b.z; acc[5][3] += a1.y * b.w;
            acc[6][0] += a1.z * b.x; acc[6][1] += a1.z * b.y; acc[6][2] += a1.z * b.z; acc[6][3] += a1.z * b.w;
            acc[7][0] += a1.w * b.x; acc[7][1] += a1.w * b.y; acc[7][2] += a1.w * b.z; acc[7][3] += a1.w * b.w;
        }
        __syncthreads();
    }
#pragma unroll
    for (int i = 0; i < 8; i++) {
        int row = rowBase + ty * 8 + i;
        if (row < N) {
            *(float4*)&H[(size_t)row * 64 + tx * 4] =
                make_float4(acc[i][0], acc[i][1], acc[i][2], acc[i][3]);
        }
    }
}

// ---------------------------------------------------------------------------
// GEMM2: C[N,128] = X[N,64] * W[64,128], whole-K in smem, A transposed
// ---------------------------------------------------------------------------
__global__ __launch_bounds__(256) void gemm2_kernel(
    const float* __restrict__ X, const float* __restrict__ W,
    float* __restrict__ H, int N)
{
    __shared__ float As[64][64];   // [k][row]
    __shared__ float Bs[64][128];  // [k][col]
    const int tid = threadIdx.x;
    const int tx = tid & 15;       // 16 col-groups of 8
    const int ty = tid >> 4;       // 16 row-groups of 4
    const int rowBase = blockIdx.x * 64;

#pragma unroll
    for (int i = tid; i < 2048; i += 256) {
        int r = i >> 5, c4 = (i & 31) << 2;
        *(float4*)&Bs[r][c4] = *(const float4*)&W[(size_t)r * 128 + c4];
    }
#pragma unroll
    for (int i = tid; i < 1024; i += 256) {
        int r = i >> 4, c4 = (i & 15) << 2;
        int row = rowBase + r;
        float4 v = make_float4(0.f, 0.f, 0.f, 0.f);
        if (row < N) v = *(const float4*)&X[(size_t)row * 64 + c4];
        As[c4 + 0][r] = v.x; As[c4 + 1][r] = v.y; As[c4 + 2][r] = v.z; As[c4 + 3][r] = v.w;
    }
    __syncthreads();

    float acc[4][8];
#pragma unroll
    for (int i = 0; i < 4; i++)
#pragma unroll
        for (int j = 0; j < 8; j++) acc[i][j] = 0.f;

#pragma unroll 8
    for (int k = 0; k < 64; k++) {
        float a0 = As[k][ty * 4 + 0];
        float a1 = As[k][ty * 4 + 1];
        float a2 = As[k][ty * 4 + 2];
        float a3 = As[k][ty * 4 + 3];
        float4 b0 = *(float4*)&Bs[k][tx * 8];
        float4 b1 = *(float4*)&Bs[k][tx * 8 + 4];
        acc[0][0] += a0 * b0.x; acc[0][1] += a0 * b0.y; acc[0][2] += a0 * b0.z; acc[0][3] += a0 * b0.w;
        acc[0][4] += a0 * b1.x; acc[0][5] += a0 * b1.y; acc[0][6] += a0 * b1.z; acc[0][7] += a0 * b1.w;
        acc[1][0] += a1 * b0.x; acc[1][1] += a1 * b0.y; acc[1][2] += a1 * b0.z; acc[1][3] += a1 * b0.w;
        acc[1][4] += a1 * b1.x; acc[1][5] += a1 * b1.y; acc[1][6] += a1 * b1.z; acc[1][7] += a1 * b1.w;
        acc[2][0] += a2 * b0.x; acc[2][1] += a2 * b0.y; acc[2][2] += a2 * b0.z; acc[2][3] += a2 * b0.w;
        acc[2][4] += a2 * b1.x; acc[2][5] += a2 * b1.y; acc[2][6] += a2 * b1.z; acc[2][7] += a2 * b1.w;
        acc[3][0] += a3 * b0.x; acc[3][1] += a3 * b0.y; acc[3][2] += a3 * b0.z; acc[3][3] += a3 * b0.w;
        acc[3][4] += a3 * b1.x; acc[3][5] += a3 * b1.y; acc[3][6] += a3 * b1.z; acc[3][7] += a3 * b1.w;
    }
#pragma unroll
    for (int i = 0; i < 4; i++) {
        int row = rowBase + ty * 4 + i;
        if (row < N) {
            *(float4*)&H[(size_t)row * 128 + tx * 8] =
                make_float4(acc[i][0], acc[i][1], acc[i][2], acc[i][3]);
            *(float4*)&H[(size_t)row * 128 + tx * 8 + 4] =
                make_float4(acc[i][4], acc[i][5], acc[i][6], acc[i][7]);
        }
    }
}

// ---------------------------------------------------------------------------
// Per-node attention coefficients: as[n,h] = sum_c h[n,h,c]*a_src[h,c]
// ---------------------------------------------------------------------------
template <int C>
__global__ __launch_bounds__(256) void alpha_kernel(
    const float* __restrict__ H, const float* __restrict__ a_s,
    const float* __restrict__ a_d, float* __restrict__ as_o,
    float* __restrict__ ad_o, int N)
{
    int i = blockIdx.x * blockDim.x + threadIdx.x;
    if (i >= N * 8) return;
    int n = i >> 3, h = i & 7;
    const float* hp = H + (size_t)n * 8 * C + h * C;
    float s = 0.f, d = 0.f;
#pragma unroll
    for (int c = 0; c < C; c++) {
        float v = __ldg(&hp[c]);
        s += v * __ldg(&a_s[h * C + c]);
        d += v * __ldg(&a_d[h * C + c]);
    }
    as_o[i] = s;
    ad_o[i] = d;
}

// ---------------------------------------------------------------------------
// CSR build: histogram -> exclusive scan (3 kernels) -> fill
// ---------------------------------------------------------------------------
__global__ __launch_bounds__(256) void hist_kernel(
    const int* __restrict__ dst, int* __restrict__ deg, int E)
{
    int e = blockIdx.x * blockDim.x + threadIdx.x;
    if (e < E) atomicAdd(&deg[__ldg(&dst[e])], 1);
}

// Block-level exclusive scan: 1024 elems/block (4 per thread), 256 threads.
__global__ __launch_bounds__(256) void scan_partial_kernel(
    const int* __restrict__ deg, int* __restrict__ off,
    int* __restrict__ blockSums, int N)
{
    __shared__ int warpSums[8];
    int tid = threadIdx.x;
    int base = blockIdx.x * 1024 + tid * 4;
    int d0 = base + 0 < N ? deg[base + 0] : 0;
    int d1 = base + 1 < N ? deg[base + 1] : 0;
    int d2 = base + 2 < N ? deg[base + 2] : 0;
    int d3 = base + 3 < N ? deg[base + 3] : 0;
    int s = d0 + d1 + d2 + d3;

    int lane = tid & 31, wid = tid >> 5;
    int v = s;
#pragma unroll
    for (int o = 1; o < 32; o <<= 1) {
        int t = __shfl_up_sync(0xffffffffu, v, o);
        if (lane >= o) v += t;
    }
    if (lane == 31) warpSums[wid] = v;
    __syncthreads();
    if (wid == 0) {
        int w = lane < 8 ? warpSums[lane] : 0;
#pragma unroll
        for (int o = 1; o < 8; o <<= 1) {
            int t = __shfl_up_sync(0xffffffffu, w, o);
            if (lane >= o) w += t;
        }
        if (lane < 8) warpSums[lane] = w;
    }
    __syncthreads();
    int ex = v - s + (wid ? warpSums[wid - 1] : 0);
    if (base + 0 < N) off[base + 0] = ex;
    if (base + 1 < N) off[base + 1] = ex + d0;
    if (base + 2 < N) off[base + 2] = ex + d0 + d1;
    if (base + 3 < N) off[base + 3] = ex + d0 + d1 + d2;
    if (tid == 255) blockSums[blockIdx.x] = warpSums[7];
}

__global__ void scan_sums_kernel(int* __restrict__ blockSums, int nb)
{
    __shared__ int sm[1024];
    int t = threadIdx.x;
    for (int i = t; i < nb; i += blockDim.x) sm[i] = blockSums[i];
    __syncthreads();
    if (t == 0) {
        int run = 0;
        for (int i = 0; i < nb; i++) { int v = sm[i]; sm[i] = run; run += v; }
    }
    __syncthreads();
    for (int i = t; i < nb; i += blockDim.x) blockSums[i] = sm[i];
}

// Reads block sums from a DEDICATED buffer (bsum); writes both off and
// cursor. No aliasing: bsum is never written here.
__global__ __launch_bounds__(256) void scan_add_kernel(
    int* __restrict__ off, const int* __restrict__ bsum,
    int* __restrict__ cursorOut, int N)
{
    int i = blockIdx.x * blockDim.x + threadIdx.x;
    if (i < N) {
        int v = off[i] + __ldg(&bsum[i >> 10]);
        off[i] = v;
        cursorOut[i] = v;
    }
}

__global__ __launch_bounds__(256) void fill_kernel(
    const int* __restrict__ src, const int* __restrict__ dst,
    int* __restrict__ cursor, int* __restrict__ csr, int E)
{
    int e = blockIdx.x * blockDim.x + threadIdx.x;
    if (e >= E) return;
    int d = __ldg(&dst[e]);
    int pos = atomicAdd(&cursor[d], 1);
    csr[pos] = __ldg(&src[e]);
}

// ---------------------------------------------------------------------------
// Layer-1 aggregation (gather): warp per dst node. 64 ch, float2/lane.
// Manually software-pipelined 2-wide: two independent load groups in flight.
// Fuses softmax normalization + bias + ELU. No atomics.
// ---------------------------------------------------------------------------
__global__ __launch_bounds__(256) void agg1_kernel(
    const int* __restrict__ csr, const int* __restrict__ off,
    const int* __restrict__ deg, const float* __restrict__ as,
    const float* __restrict__ ad, const float* __restrict__ H,
    const float* __restrict__ b, float* __restrict__ OUT, int N)
{
    int d = (blockIdx.x * blockDim.x + threadIdx.x) >> 5;
    if (d >= N) return;
    int lane = threadIdx.x & 31;
    int h = lane >> 2;          // 8 heads x 4 lanes, 2 ch per lane
    int c2 = lane * 2;

    float adh = __ldg(&ad[(size_t)d * 8 + h]);

    // self loop
    float ev = __ldg(&as[(size_t)d * 8 + h]) + adh;
    ev = ev > 0.f ? ev : 0.2f * ev;
    float ex = __expf(ev);
    float2 v = __ldg((const float2*)&H[(size_t)d * 64 + c2]);
    float ax = ex * v.x, ay = ex * v.y, den = ex;
    float ax2 = 0.f, ay2 = 0.f, den2 = 0.f;   // second accumulator chain

    int beg = __ldg(&off[d]);
    int cnt = __ldg(&deg[d]);
    int j = 0;
    for (; j + 2 <= cnt; j += 2) {
        int s0 = __ldg(&csr[beg + j]);
        int s1 = __ldg(&csr[beg + j + 1]);
        float e0 = __ldg(&as[(size_t)s0 * 8 + h]);
        float e1 = __ldg(&as[(size_t)s1 * 8 + h]);
        float2 u0 = __ldg((const float2*)&H[(size_t)s0 * 64 + c2]);
        float2 u1 = __ldg((const float2*)&H[(size_t)s1 * 64 + c2]);
        e0 += adh; e0 = e0 > 0.f ? e0 : 0.2f * e0; float x0 = __expf(e0);
        e1 += adh; e1 = e1 > 0.f ? e1 : 0.2f * e1; float x1 = __expf(e1);
        ax  += x0 * u0.x; ay  += x0 * u0.y; den  += x0;
        ax2 += x1 * u1.x; ay2 += x1 * u1.y; den2 += x1;
    }
    if (j < cnt) {
        int s0 = __ldg(&csr[beg + j]);
        float e0 = __ldg(&as[(size_t)s0 * 8 + h]) + adh;
        e0 = e0 > 0.f ? e0 : 0.2f * e0;
        float x0 = __expf(e0);
        float2 u0 = __ldg((const float2*)&H[(size_t)s0 * 64 + c2]);
        ax += x0 * u0.x; ay += x0 * u0.y; den += x0;
    }
    ax += ax2; ay += ay2; den += den2;

    float inv = 1.f / den;
    float o0 = ax * inv + __ldg(&b[c2]);
    float o1 = ay * inv + __ldg(&b[c2 + 1]);
    o0 = o0 > 0.f ? o0 : (__expf(o0) - 1.f);
    o1 = o1 > 0.f ? o1 : (__expf(o1) - 1.f);
    *(float2*)&OUT[(size_t)d * 64 + c2] = make_float2(o0, o1);
}

// ---------------------------------------------------------------------------
// Layer-2 aggregation (gather): warp per dst node. 128 ch, float4/lane.
// Software-pipelined 2-wide. Fuses normalization + head-mean + bias.
// ---------------------------------------------------------------------------
__global__ __launch_bounds__(256) void agg2_kernel(
    const int* __restrict__ csr, const int* __restrict__ off,
    const int* __restrict__ deg, const float* __restrict__ as,
    const float* __restrict__ ad, const float* __restrict__ H,
    const float* __restrict__ b, float* __restrict__ OUT, int N)
{
    int d = (blockIdx.x * blockDim.x + threadIdx.x) >> 5;
    if (d >= N) return;
    int lane = threadIdx.x & 31;
    int h = lane >> 2;          // 8 heads x 4 lanes, 4 ch per lane
    int c4 = lane * 4;

    float adh = __ldg(&ad[(size_t)d * 8 + h]);

    // self loop
    float ev = __ldg(&as[(size_t)d * 8 + h]) + adh;
    ev = ev > 0.f ? ev : 0.2f * ev;
    float ex = __expf(ev);
    float4 v = __ldg((const float4*)&H[(size_t)d * 128 + c4]);
    float a0 = ex * v.x, a1 = ex * v.y, a2 = ex * v.z, a3 = ex * v.w;
    float den = ex;
    float b0a = 0.f, b1a = 0.f, b2a = 0.f, b3a = 0.f, den2 = 0.f;

    int beg = __ldg(&off[d]);
    int cnt = __ldg(&deg[d]);
    int j = 0;
    for (; j + 2 <= cnt; j += 2) {
        int s0 = __ldg(&csr[beg + j]);
        int s1 = __ldg(&csr[beg + j + 1]);
        float e0 = __ldg(&as[(size_t)s0 * 8 + h]);
        float e1 = __ldg(&as[(size_t)s1 * 8 + h]);
        float4 u0 = __ldg((const float4*)&H[(size_t)s0 * 128 + c4]);
        float4 u1 = __ldg((const float4*)&H[(size_t)s1 * 128 + c4]);
        e0 += adh; e0 = e0 > 0.f ? e0 : 0.2f * e0; float x0 = __expf(e0);
        e1 += adh; e1 = e1 > 0.f ? e1 : 0.2f * e1; float x1 = __expf(e1);
        a0  += x0 * u0.x; a1  += x0 * u0.y; a2  += x0 * u0.z; a3  += x0 * u0.w; den  += x0;
        b0a += x1 * u1.x; b1a += x1 * u1.y; b2a += x1 * u1.z; b3a += x1 * u1.w; den2 += x1;
    }
    if (j < cnt) {
        int s0 = __ldg(&csr[beg + j]);
        float e0 = __ldg(&as[(size_t)s0 * 8 + h]) + adh;
        e0 = e0 > 0.f ? e0 : 0.2f * e0;
        float x0 = __expf(e0);
        float4 u0 = __ldg((const float4*)&H[(size_t)s0 * 128 + c4]);
        a0 += x0 * u0.x; a1 += x0 * u0.y; a2 += x0 * u0.z; a3 += x0 * u0.w; den += x0;
    }
    a0 += b0a; a1 += b1a; a2 += b2a; a3 += b3a; den += den2;

    float inv = 1.f / den;
    a0 *= inv; a1 *= inv; a2 *= inv; a3 *= inv;

    // mean over heads: head index = bits [2:4] of lane -> butterfly over 4,8,16
#pragma unroll
    for (int o = 4; o <= 16; o <<= 1) {
        a0 += __shfl_xor_sync(0xffffffffu, a0, o);
        a1 += __shfl_xor_sync(0xffffffffu, a1, o);
        a2 += __shfl_xor_sync(0xffffffffu, a2, o);
        a3 += __shfl_xor_sync(0xffffffffu, a3, o);
    }
    if (lane < 4) {
        int c = lane * 4;
        float4 o4 = make_float4(
            a0 * 0.125f + __ldg(&b[c]),
            a1 * 0.125f + __ldg(&b[c + 1]),
            a2 * 0.125f + __ldg(&b[c + 2]),
            a3 * 0.125f + __ldg(&b[c + 3]));
        *(float4*)&OUT[(size_t)d * 16 + c] = o4;
    }
}

// ---------------------------------------------------------------------------
extern "C" void kernel_launch(void* const* d_in, const int* in_sizes, int n_in,
                              void* d_out, int out_size)
{
    const float* x      = (const float*)d_in[0];
    const int*   ei     = (const int*)  d_in[1];
    const float* W1     = (const float*)d_in[2];
    const float* a_src1 = (const float*)d_in[3];
    const float* a_dst1 = (const float*)d_in[4];
    const float* b1     = (const float*)d_in[5];
    const float* W2     = (const float*)d_in[6];
    const float* a_src2 = (const float*)d_in[7];
    const float* a_dst2 = (const float*)d_in[8];
    const float* b2     = (const float*)d_in[9];

    const int N = in_sizes[0] / 512;
    const int E = in_sizes[1] / 2;
    const int* src = ei;
    const int* dst = ei + E;

    float *h1, *as1, *ad1, *acc1, *h2, *as2, *ad2;
    int *deg, *off, *cursor, *bsum, *csr;
    cudaGetSymbolAddress((void**)&h1,   g_h1);
    cudaGetSymbolAddress((void**)&as1,  g_as1);
    cudaGetSymbolAddress((void**)&ad1,  g_ad1);
    cudaGetSymbolAddress((void**)&acc1, g_acc1);
    cudaGetSymbolAddress((void**)&h2,   g_h2);
    cudaGetSymbolAddress((void**)&as2,  g_as2);
    cudaGetSymbolAddress((void**)&ad2,  g_ad2);
    cudaGetSymbolAddress((void**)&deg,    g_deg);
    cudaGetSymbolAddress((void**)&off,    g_off);
    cudaGetSymbolAddress((void**)&cursor, g_cursor);
    cudaGetSymbolAddress((void**)&bsum,   g_bsum);
    cudaGetSymbolAddress((void**)&csr,    g_csr);

    const int nb = cdiv(N, 1024);

    // ---- Fork: CSR build on side stream, concurrent with layer-1 GEMM ----
    cudaEventRecord(g_evFork, 0);
    cudaStreamWaitEvent(g_s1, g_evFork, 0);

    cudaMemsetAsync(deg, 0, (size_t)N * sizeof(int), g_s1);
    hist_kernel<<<cdiv(E, 256), 256, 0, g_s1>>>(dst, deg, E);
    scan_partial_kernel<<<nb, 256, 0, g_s1>>>(deg, off, bsum, N);
    scan_sums_kernel<<<1, 256, 0, g_s1>>>(bsum, nb);
    scan_add_kernel<<<cdiv(N, 256), 256, 0, g_s1>>>(off, bsum, cursor, N);
    fill_kernel<<<cdiv(E, 256), 256, 0, g_s1>>>(src, dst, cursor, csr, E);
    cudaEventRecord(g_evJoin, g_s1);

    // ---- Layer 1 (main stream, concurrent with CSR build) ----
    gemm1_kernel<<<cdiv(N, 128), 256>>>(x, W1, h1, N);
    alpha_kernel<8><<<cdiv(N * 8, 256), 256>>>(h1, a_src1, a_dst1, as1, ad1, N);

    cudaStreamWaitEvent(0, g_evJoin, 0);   // join: agg1 needs CSR
    agg1_kernel<<<cdiv(N * 32, 256), 256>>>(csr, off, deg, as1, ad1, h1, b1, acc1, N);

    // ---- Layer 2 ----
    gemm2_kernel<<<cdiv(N, 64), 256>>>(acc1, W2, h2, N);
    alpha_kernel<16><<<cdiv(N * 8, 256), 256>>>(h2, a_src2, a_dst2, as2, ad2, N);
    agg2_kernel<<<cdiv(N * 32, 256), 256>>>(csr, off, deg, as2, ad2, h2, b2, (float*)d_out, N);
}

// round 13
// speedup vs baseline: 2.4616x; 1.0092x over previous
#include <cuda_runtime.h>
#include <cstdint>
#include <cstddef>

// Problem-size capacities (fixed dataset: N=100000, E=3200000)
#define MAXN 100000
#define MAXE 3200000

// Scratch: __device__ globals (no allocation allowed)
__device__ float g_h1[MAXN * 64];     // layer1 features h = xW1  [N,8,8]
__device__ float g_as1[MAXN * 8];
__device__ float g_ad1[MAXN * 8];
__device__ float g_acc1[MAXN * 64];   // layer1 output (elu'd) -> layer2 input
__device__ float g_h2[MAXN * 128];    // layer2 features [N,8,16]
__device__ float g_as2[MAXN * 8];
__device__ float g_ad2[MAXN * 8];
// CSR scratch
__device__ int g_deg[MAXN];
__device__ int g_off[MAXN];
__device__ int g_cursor[MAXN];
__device__ int g_bsum[128];           // scan block sums (nb = ceil(N/1024) <= 98)
__device__ int g_csr[MAXE];

static inline int cdiv(int a, int b) { return (a + b - 1) / b; }

// Side stream + fork/join events, created once at static init (no device
// memory allocation involved — streams/events are driver objects).
static cudaStream_t g_s1;
static cudaEvent_t g_evFork, g_evJoin;
namespace {
struct StreamInit {
    StreamInit() {
        cudaStreamCreateWithFlags(&g_s1, cudaStreamNonBlocking);
        cudaEventCreateWithFlags(&g_evFork, cudaEventDisableTiming);
        cudaEventCreateWithFlags(&g_evJoin, cudaEventDisableTiming);
    }
} s_streamInit;
}

// ---------------------------------------------------------------------------
// TF32 helpers
// ---------------------------------------------------------------------------
__device__ __forceinline__ uint32_t f2tf32(float x) {
    uint32_t r;
    asm("cvt.rna.tf32.f32 %0, %1;" : "=r"(r) : "f"(x));
    return r;
}

__device__ __forceinline__ void mma_tf32(float* c, const uint32_t* a, const uint32_t* b) {
    asm volatile(
        "mma.sync.aligned.m16n8k8.row.col.f32.tf32.tf32.f32 "
        "{%0,%1,%2,%3}, {%4,%5,%6,%7}, {%8,%9}, {%0,%1,%2,%3};"
        : "+f"(c[0]), "+f"(c[1]), "+f"(c[2]), "+f"(c[3])
        : "r"(a[0]), "r"(a[1]), "r"(a[2]), "r"(a[3]), "r"(b[0]), "r"(b[1]));
}

// ---------------------------------------------------------------------------
// GEMM1 (3xTF32 tensor core): C[N,64] = X[N,512] * W[512,64].
// Block tile 128x64, 8 warps (m16 each), K-chunks of 16.
// hi/lo split: x = hi + lo (+eps); x*w ~= hi*whi + hi*wlo + lo*whi.
// Residual ~2^-22 per term -> end-to-end error ~1e-7, fp32-class.
// Smem padding: A row-stride 136 words, B row-stride 72 words ->
// fragment LDS addresses (k*8 + r) mod 32 all distinct = conflict-free.
// ---------------------------------------------------------------------------
__global__ __launch_bounds__(256) void gemm1_tf32_kernel(
    const float* __restrict__ X, const float* __restrict__ W,
    float* __restrict__ H, int N)
{
    __shared__ uint32_t AhiS[16][136];  // [k][row], rows 0..127
    __shared__ uint32_t AloS[16][136];
    __shared__ uint32_t BhiS[16][72];   // [k][n], n 0..63
    __shared__ uint32_t BloS[16][72];

    const int tid = threadIdx.x;
    const int lane = tid & 31;
    const int warp = tid >> 5;          // 0..7
    const int wbase = warp * 16;        // warp's row range within tile
    const int rowBase = blockIdx.x * 128;
    const int gr = lane >> 2;           // fragment group row (0..7)
    const int gc = lane & 3;            // fragment group col (0..3)

    float acc[8][4];                    // 8 n-tiles x 4 regs
#pragma unroll
    for (int i = 0; i < 8; i++)
#pragma unroll
        for (int j = 0; j < 4; j++) acc[i][j] = 0.f;

    for (int k0 = 0; k0 < 512; k0 += 16) {
        // ---- load A chunk: 128 rows x 16 k. 512 float4 / 256 thr = 2 each.
#pragma unroll
        for (int p = tid; p < 512; p += 256) {
            int r = p >> 2;             // row in tile
            int c4 = (p & 3) << 2;      // k offset (0,4,8,12)
            int row = rowBase + r;
            float4 v = make_float4(0.f, 0.f, 0.f, 0.f);
            if (row < N) v = *(const float4*)&X[(size_t)row * 512 + k0 + c4];
            float xs[4] = {v.x, v.y, v.z, v.w};
#pragma unroll
            for (int j = 0; j < 4; j++) {
                uint32_t hi = f2tf32(xs[j]);
                float lo = xs[j] - __uint_as_float(hi);
                AhiS[c4 + j][r] = hi;
                AloS[c4 + j][r] = f2tf32(lo);
            }
        }
        // ---- load B chunk: 16 k x 64 n. 256 float4 / 256 thr = 1 each.
        {
            int p = tid;
            int k = p >> 4;
            int c4 = (p & 15) << 2;
            float4 v = *(const float4*)&W[(size_t)(k0 + k) * 64 + c4];
            float xs[4] = {v.x, v.y, v.z, v.w};
#pragma unroll
            for (int j = 0; j < 4; j++) {
                uint32_t hi = f2tf32(xs[j]);
                float lo = xs[j] - __uint_as_float(hi);
                BhiS[k][c4 + j] = hi;
                BloS[k][c4 + j] = f2tf32(lo);
            }
        }
        __syncthreads();

        // ---- 2 k-steps of m16n8k8 per chunk
#pragma unroll
        for (int ks = 0; ks < 2; ks++) {
            int kb = ks * 8 + gc;
            uint32_t ahi[4], alo[4];
            ahi[0] = AhiS[kb][wbase + gr];
            ahi[1] = AhiS[kb][wbase + gr + 8];
            ahi[2] = AhiS[kb + 4][wbase + gr];
            ahi[3] = AhiS[kb + 4][wbase + gr + 8];
            alo[0] = AloS[kb][wbase + gr];
            alo[1] = AloS[kb][wbase + gr + 8];
            alo[2] = AloS[kb + 4][wbase + gr];
            alo[3] = AloS[kb + 4][wbase + gr + 8];
#pragma unroll
            for (int nt = 0; nt < 8; nt++) {
                uint32_t bhi[2], blo[2];
                int nn = nt * 8 + gr;
                bhi[0] = BhiS[kb][nn];
                bhi[1] = BhiS[kb + 4][nn];
                blo[0] = BloS[kb][nn];
                blo[1] = BloS[kb + 4][nn];
                mma_tf32(acc[nt], ahi, bhi);
                mma_tf32(acc[nt], ahi, blo);
                mma_tf32(acc[nt], alo, bhi);
            }
        }
        __syncthreads();
    }

    // ---- store: thread owns rows (wbase+gr, +8), cols nt*8 + 2*gc (+1)
    int r0 = rowBase + wbase + gr;
    int r1 = r0 + 8;
#pragma unroll
    for (int nt = 0; nt < 8; nt++) {
        int col = nt * 8 + gc * 2;
        if (r0 < N)
            *(float2*)&H[(size_t)r0 * 64 + col] = make_float2(acc[nt][0], acc[nt][1]);
        if (r1 < N)
            *(float2*)&H[(size_t)r1 * 64 + col] = make_float2(acc[nt][2], acc[nt][3]);
    }
}

// ---------------------------------------------------------------------------
// GEMM2: C[N,128] = X[N,64] * W[64,128], whole-K in smem, A transposed (fp32)
// ---------------------------------------------------------------------------
__global__ __launch_bounds__(256) void gemm2_kernel(
    const float* __restrict__ X, const float* __restrict__ W,
    float* __restrict__ H, int N)
{
    __shared__ float As[64][64];   // [k][row]
    __shared__ float Bs[64][128];  // [k][col]
    const int tid = threadIdx.x;
    const int tx = tid & 15;       // 16 col-groups of 8
    const int ty = tid >> 4;       // 16 row-groups of 4
    const int rowBase = blockIdx.x * 64;

#pragma unroll
    for (int i = tid; i < 2048; i += 256) {
        int r = i >> 5, c4 = (i & 31) << 2;
        *(float4*)&Bs[r][c4] = *(const float4*)&W[(size_t)r * 128 + c4];
    }
#pragma unroll
    for (int i = tid; i < 1024; i += 256) {
        int r = i >> 4, c4 = (i & 15) << 2;
        int row = rowBase + r;
        float4 v = make_float4(0.f, 0.f, 0.f, 0.f);
        if (row < N) v = *(const float4*)&X[(size_t)row * 64 + c4];
        As[c4 + 0][r] = v.x; As[c4 + 1][r] = v.y; As[c4 + 2][r] = v.z; As[c4 + 3][r] = v.w;
    }
    __syncthreads();

    float acc[4][8];
#pragma unroll
    for (int i = 0; i < 4; i++)
#pragma unroll
        for (int j = 0; j < 8; j++) acc[i][j] = 0.f;

#pragma unroll 8
    for (int k = 0; k < 64; k++) {
        float a0 = As[k][ty * 4 + 0];
        float a1 = As[k][ty * 4 + 1];
        float a2 = As[k][ty * 4 + 2];
        float a3 = As[k][ty * 4 + 3];
        float4 b0 = *(float4*)&Bs[k][tx * 8];
        float4 b1 = *(float4*)&Bs[k][tx * 8 + 4];
        acc[0][0] += a0 * b0.x; acc[0][1] += a0 * b0.y; acc[0][2] += a0 * b0.z; acc[0][3] += a0 * b0.w;
        acc[0][4] += a0 * b1.x; acc[0][5] += a0 * b1.y; acc[0][6] += a0 * b1.z; acc[0][7] += a0 * b1.w;
        acc[1][0] += a1 * b0.x; acc[1][1] += a1 * b0.y; acc[1][2] += a1 * b0.z; acc[1][3] += a1 * b0.w;
        acc[1][4] += a1 * b1.x; acc[1][5] += a1 * b1.y; acc[1][6] += a1 * b1.z; acc[1][7] += a1 * b1.w;
        acc[2][0] += a2 * b0.x; acc[2][1] += a2 * b0.y; acc[2][2] += a2 * b0.z; acc[2][3] += a2 * b0.w;
        acc[2][4] += a2 * b1.x; acc[2][5] += a2 * b1.y; acc[2][6] += a2 * b1.z; acc[2][7] += a2 * b1.w;
        acc[3][0] += a3 * b0.x; acc[3][1] += a3 * b0.y; acc[3][2] += a3 * b0.z; acc[3][3] += a3 * b0.w;
        acc[3][4] += a3 * b1.x; acc[3][5] += a3 * b1.y; acc[3][6] += a3 * b1.z; acc[3][7] += a3 * b1.w;
    }
#pragma unroll
    for (int i = 0; i < 4; i++) {
        int row = rowBase + ty * 4 + i;
        if (row < N) {
            *(float4*)&H[(size_t)row * 128 + tx * 8] =
                make_float4(acc[i][0], acc[i][1], acc[i][2], acc[i][3]);
            *(float4*)&H[(size_t)row * 128 + tx * 8 + 4] =
                make_float4(acc[i][4], acc[i][5], acc[i][6], acc[i][7]);
        }
    }
}

// ---------------------------------------------------------------------------
// Per-node attention coefficients: as[n,h] = sum_c h[n,h,c]*a_src[h,c]
// ---------------------------------------------------------------------------
template <int C>
__global__ __launch_bounds__(256) void alpha_kernel(
    const float* __restrict__ H, const float* __restrict__ a_s,
    const float* __restrict__ a_d, float* __restrict__ as_o,
    float* __restrict__ ad_o, int N)
{
    int i = blockIdx.x * blockDim.x + threadIdx.x;
    if (i >= N * 8) return;
    int n = i >> 3, h = i & 7;
    const float* hp = H + (size_t)n * 8 * C + h * C;
    float s = 0.f, d = 0.f;
#pragma unroll
    for (int c = 0; c < C; c++) {
        float v = __ldg(&hp[c]);
        s += v * __ldg(&a_s[h * C + c]);
        d += v * __ldg(&a_d[h * C + c]);
    }
    as_o[i] = s;
    ad_o[i] = d;
}

// ---------------------------------------------------------------------------
// CSR build: histogram -> exclusive scan (3 kernels) -> fill
// ---------------------------------------------------------------------------
__global__ __launch_bounds__(256) void hist_kernel(
    const int* __restrict__ dst, int* __restrict__ deg, int E)
{
    int e = blockIdx.x * blockDim.x + threadIdx.x;
    if (e < E) atomicAdd(&deg[__ldg(&dst[e])], 1);
}

// Block-level exclusive scan: 1024 elems/block (4 per thread), 256 threads.
__global__ __launch_bounds__(256) void scan_partial_kernel(
    const int* __restrict__ deg, int* __restrict__ off,
    int* __restrict__ blockSums, int N)
{
    __shared__ int warpSums[8];
    int tid = threadIdx.x;
    int base = blockIdx.x * 1024 + tid * 4;
    int d0 = base + 0 < N ? deg[base + 0] : 0;
    int d1 = base + 1 < N ? deg[base + 1] : 0;
    int d2 = base + 2 < N ? deg[base + 2] : 0;
    int d3 = base + 3 < N ? deg[base + 3] : 0;
    int s = d0 + d1 + d2 + d3;

    int lane = tid & 31, wid = tid >> 5;
    int v = s;
#pragma unroll
    for (int o = 1; o < 32; o <<= 1) {
        int t = __shfl_up_sync(0xffffffffu, v, o);
        if (lane >= o) v += t;
    }
    if (lane == 31) warpSums[wid] = v;
    __syncthreads();
    if (wid == 0) {
        int w = lane < 8 ? warpSums[lane] : 0;
#pragma unroll
        for (int o = 1; o < 8; o <<= 1) {
            int t = __shfl_up_sync(0xffffffffu, w, o);
            if (lane >= o) w += t;
        }
        if (lane < 8) warpSums[lane] = w;
    }
    __syncthreads();
    int ex = v - s + (wid ? warpSums[wid - 1] : 0);
    if (base + 0 < N) off[base + 0] = ex;
    if (base + 1 < N) off[base + 1] = ex + d0;
    if (base + 2 < N) off[base + 2] = ex + d0 + d1;
    if (base + 3 < N) off[base + 3] = ex + d0 + d1 + d2;
    if (tid == 255) blockSums[blockIdx.x] = warpSums[7];
}

__global__ void scan_sums_kernel(int* __restrict__ blockSums, int nb)
{
    __shared__ int sm[1024];
    int t = threadIdx.x;
    for (int i = t; i < nb; i += blockDim.x) sm[i] = blockSums[i];
    __syncthreads();
    if (t == 0) {
        int run = 0;
        for (int i = 0; i < nb; i++) { int v = sm[i]; sm[i] = run; run += v; }
    }
    __syncthreads();
    for (int i = t; i < nb; i += blockDim.x) blockSums[i] = sm[i];
}

// Reads block sums from a DEDICATED buffer (bsum); writes both off and
// cursor. No aliasing: bsum is never written here.
__global__ __launch_bounds__(256) void scan_add_kernel(
    int* __restrict__ off, const int* __restrict__ bsum,
    int* __restrict__ cursorOut, int N)
{
    int i = blockIdx.x * blockDim.x + threadIdx.x;
    if (i < N) {
        int v = off[i] + __ldg(&bsum[i >> 10]);
        off[i] = v;
        cursorOut[i] = v;
    }
}

__global__ __launch_bounds__(256) void fill_kernel(
    const int* __restrict__ src, const int* __restrict__ dst,
    int* __restrict__ cursor, int* __restrict__ csr, int E)
{
    int e = blockIdx.x * blockDim.x + threadIdx.x;
    if (e >= E) return;
    int d = __ldg(&dst[e]);
    int pos = atomicAdd(&cursor[d], 1);
    csr[pos] = __ldg(&src[e]);
}

// ---------------------------------------------------------------------------
// Layer-1 aggregation (gather): warp per dst node. 64 ch, float2/lane.
// Software-pipelined 2-wide. Fuses softmax norm + bias + ELU. No atomics.
// ---------------------------------------------------------------------------
__global__ __launch_bounds__(256) void agg1_kernel(
    const int* __restrict__ csr, const int* __restrict__ off,
    const int* __restrict__ deg, const float* __restrict__ as,
    const float* __restrict__ ad, const float* __restrict__ H,
    const float* __restrict__ b, float* __restrict__ OUT, int N)
{
    int d = (blockIdx.x * blockDim.x + threadIdx.x) >> 5;
    if (d >= N) return;
    int lane = threadIdx.x & 31;
    int h = lane >> 2;          // 8 heads x 4 lanes, 2 ch per lane
    int c2 = lane * 2;

    float adh = __ldg(&ad[(size_t)d * 8 + h]);

    // self loop
    float ev = __ldg(&as[(size_t)d * 8 + h]) + adh;
    ev = ev > 0.f ? ev : 0.2f * ev;
    float ex = __expf(ev);
    float2 v = __ldg((const float2*)&H[(size_t)d * 64 + c2]);
    float ax = ex * v.x, ay = ex * v.y, den = ex;
    float ax2 = 0.f, ay2 = 0.f, den2 = 0.f;   // second accumulator chain

    int beg = __ldg(&off[d]);
    int cnt = __ldg(&deg[d]);
    int j = 0;
    for (; j + 2 <= cnt; j += 2) {
        int s0 = __ldg(&csr[beg + j]);
        int s1 = __ldg(&csr[beg + j + 1]);
        float e0 = __ldg(&as[(size_t)s0 * 8 + h]);
        float e1 = __ldg(&as[(size_t)s1 * 8 + h]);
        float2 u0 = __ldg((const float2*)&H[(size_t)s0 * 64 + c2]);
        float2 u1 = __ldg((const float2*)&H[(size_t)s1 * 64 + c2]);
        e0 += adh; e0 = e0 > 0.f ? e0 : 0.2f * e0; float x0 = __expf(e0);
        e1 += adh; e1 = e1 > 0.f ? e1 : 0.2f * e1; float x1 = __expf(e1);
        ax  += x0 * u0.x; ay  += x0 * u0.y; den  += x0;
        ax2 += x1 * u1.x; ay2 += x1 * u1.y; den2 += x1;
    }
    if (j < cnt) {
        int s0 = __ldg(&csr[beg + j]);
        float e0 = __ldg(&as[(size_t)s0 * 8 + h]) + adh;
        e0 = e0 > 0.f ? e0 : 0.2f * e0;
        float x0 = __expf(e0);
        float2 u0 = __ldg((const float2*)&H[(size_t)s0 * 64 + c2]);
        ax += x0 * u0.x; ay += x0 * u0.y; den += x0;
    }
    ax += ax2; ay += ay2; den += den2;

    float inv = 1.f / den;
    float o0 = ax * inv + __ldg(&b[c2]);
    float o1 = ay * inv + __ldg(&b[c2 + 1]);
    o0 = o0 > 0.f ? o0 : (__expf(o0) - 1.f);
    o1 = o1 > 0.f ? o1 : (__expf(o1) - 1.f);
    *(float2*)&OUT[(size_t)d * 64 + c2] = make_float2(o0, o1);
}

// ---------------------------------------------------------------------------
// Layer-2 aggregation (gather): warp per dst node. 128 ch, float4/lane.
// Software-pipelined 2-wide. Fuses normalization + head-mean + bias.
// ---------------------------------------------------------------------------
__global__ __launch_bounds__(256) void agg2_kernel(
    const int* __restrict__ csr, const int* __restrict__ off,
    const int* __restrict__ deg, const float* __restrict__ as,
    const float* __restrict__ ad, const float* __restrict__ H,
    const float* __restrict__ b, float* __restrict__ OUT, int N)
{
    int d = (blockIdx.x * blockDim.x + threadIdx.x) >> 5;
    if (d >= N) return;
    int lane = threadIdx.x & 31;
    int h = lane >> 2;          // 8 heads x 4 lanes, 4 ch per lane
    int c4 = lane * 4;

    float adh = __ldg(&ad[(size_t)d * 8 + h]);

    // self loop
    float ev = __ldg(&as[(size_t)d * 8 + h]) + adh;
    ev = ev > 0.f ? ev : 0.2f * ev;
    float ex = __expf(ev);
    float4 v = __ldg((const float4*)&H[(size_t)d * 128 + c4]);
    float a0 = ex * v.x, a1 = ex * v.y, a2 = ex * v.z, a3 = ex * v.w;
    float den = ex;
    float b0a = 0.f, b1a = 0.f, b2a = 0.f, b3a = 0.f, den2 = 0.f;

    int beg = __ldg(&off[d]);
    int cnt = __ldg(&deg[d]);
    int j = 0;
    for (; j + 2 <= cnt; j += 2) {
        int s0 = __ldg(&csr[beg + j]);
        int s1 = __ldg(&csr[beg + j + 1]);
        float e0 = __ldg(&as[(size_t)s0 * 8 + h]);
        float e1 = __ldg(&as[(size_t)s1 * 8 + h]);
        float4 u0 = __ldg((const float4*)&H[(size_t)s0 * 128 + c4]);
        float4 u1 = __ldg((const float4*)&H[(size_t)s1 * 128 + c4]);
        e0 += adh; e0 = e0 > 0.f ? e0 : 0.2f * e0; float x0 = __expf(e0);
        e1 += adh; e1 = e1 > 0.f ? e1 : 0.2f * e1; float x1 = __expf(e1);
        a0  += x0 * u0.x; a1  += x0 * u0.y; a2  += x0 * u0.z; a3  += x0 * u0.w; den  += x0;
        b0a += x1 * u1.x; b1a += x1 * u1.y; b2a += x1 * u1.z; b3a += x1 * u1.w; den2 += x1;
    }
    if (j < cnt) {
        int s0 = __ldg(&csr[beg + j]);
        float e0 = __ldg(&as[(size_t)s0 * 8 + h]) + adh;
        e0 = e0 > 0.f ? e0 : 0.2f * e0;
        float x0 = __expf(e0);
        float4 u0 = __ldg((const float4*)&H[(size_t)s0 * 128 + c4]);
        a0 += x0 * u0.x; a1 += x0 * u0.y; a2 += x0 * u0.z; a3 += x0 * u0.w; den += x0;
    }
    a0 += b0a; a1 += b1a; a2 += b2a; a3 += b3a; den += den2;

    float inv = 1.f / den;
    a0 *= inv; a1 *= inv; a2 *= inv; a3 *= inv;

    // mean over heads: head index = bits [2:4] of lane -> butterfly over 4,8,16
#pragma unroll
    for (int o = 4; o <= 16; o <<= 1) {
        a0 += __shfl_xor_sync(0xffffffffu, a0, o);
        a1 += __shfl_xor_sync(0xffffffffu, a1, o);
        a2 += __shfl_xor_sync(0xffffffffu, a2, o);
        a3 += __shfl_xor_sync(0xffffffffu, a3, o);
    }
    if (lane < 4) {
        int c = lane * 4;
        float4 o4 = make_float4(
            a0 * 0.125f + __ldg(&b[c]),
            a1 * 0.125f + __ldg(&b[c + 1]),
            a2 * 0.125f + __ldg(&b[c + 2]),
            a3 * 0.125f + __ldg(&b[c + 3]));
        *(float4*)&OUT[(size_t)d * 16 + c] = o4;
    }
}

// ---------------------------------------------------------------------------
extern "C" void kernel_launch(void* const* d_in, const int* in_sizes, int n_in,
                              void* d_out, int out_size)
{
    const float* x      = (const float*)d_in[0];
    const int*   ei     = (const int*)  d_in[1];
    const float* W1     = (const float*)d_in[2];
    const float* a_src1 = (const float*)d_in[3];
    const float* a_dst1 = (const float*)d_in[4];
    const float* b1     = (const float*)d_in[5];
    const float* W2     = (const float*)d_in[6];
    const float* a_src2 = (const float*)d_in[7];
    const float* a_dst2 = (const float*)d_in[8];
    const float* b2     = (const float*)d_in[9];

    const int N = in_sizes[0] / 512;
    const int E = in_sizes[1] / 2;
    const int* src = ei;
    const int* dst = ei + E;

    float *h1, *as1, *ad1, *acc1, *h2, *as2, *ad2;
    int *deg, *off, *cursor, *bsum, *csr;
    cudaGetSymbolAddress((void**)&h1,   g_h1);
    cudaGetSymbolAddress((void**)&as1,  g_as1);
    cudaGetSymbolAddress((void**)&ad1,  g_ad1);
    cudaGetSymbolAddress((void**)&acc1, g_acc1);
    cudaGetSymbolAddress((void**)&h2,   g_h2);
    cudaGetSymbolAddress((void**)&as2,  g_as2);
    cudaGetSymbolAddress((void**)&ad2,  g_ad2);
    cudaGetSymbolAddress((void**)&deg,    g_deg);
    cudaGetSymbolAddress((void**)&off,    g_off);
    cudaGetSymbolAddress((void**)&cursor, g_cursor);
    cudaGetSymbolAddress((void**)&bsum,   g_bsum);
    cudaGetSymbolAddress((void**)&csr,    g_csr);

    const int nb = cdiv(N, 1024);

    // ---- Fork: CSR build on side stream, concurrent with layer-1 GEMM ----
    cudaEventRecord(g_evFork, 0);
    cudaStreamWaitEvent(g_s1, g_evFork, 0);

    cudaMemsetAsync(deg, 0, (size_t)N * sizeof(int), g_s1);
    hist_kernel<<<cdiv(E, 256), 256, 0, g_s1>>>(dst, deg, E);
    scan_partial_kernel<<<nb, 256, 0, g_s1>>>(deg, off, bsum, N);
    scan_sums_kernel<<<1, 256, 0, g_s1>>>(bsum, nb);
    scan_add_kernel<<<cdiv(N, 256), 256, 0, g_s1>>>(off, bsum, cursor, N);
    fill_kernel<<<cdiv(E, 256), 256, 0, g_s1>>>(src, dst, cursor, csr, E);
    cudaEventRecord(g_evJoin, g_s1);

    // ---- Layer 1 (main stream, concurrent with CSR build) ----
    gemm1_tf32_kernel<<<cdiv(N, 128), 256>>>(x, W1, h1, N);
    alpha_kernel<8><<<cdiv(N * 8, 256), 256>>>(h1, a_src1, a_dst1, as1, ad1, N);

    cudaStreamWaitEvent(0, g_evJoin, 0);   // join: agg1 needs CSR
    agg1_kernel<<<cdiv(N * 32, 256), 256>>>(csr, off, deg, as1, ad1, h1, b1, acc1, N);

    // ---- Layer 2 ----
    gemm2_kernel<<<cdiv(N, 64), 256>>>(acc1, W2, h2, N);
    alpha_kernel<16><<<cdiv(N * 8, 256), 256>>>(h2, a_src2, a_dst2, as2, ad2, N);
    agg2_kernel<<<cdiv(N * 32, 256), 256>>>(csr, off, deg, as2, ad2, h2, b2, (float*)d_out, N);
}

// round 14
// speedup vs baseline: 2.6743x; 1.0864x over previous
#include <cuda_runtime.h>
#include <cstdint>
#include <cstddef>

// Problem-size capacities (fixed dataset: N=100000, E=3200000)
#define MAXN 100000
#define MAXE 3200000

// Scratch: __device__ globals (no allocation allowed)
__device__ float g_h1[MAXN * 64];     // layer1 features h = xW1  [N,8,8]
__device__ float g_as1[MAXN * 8];
__device__ float g_ad1[MAXN * 8];
__device__ float g_acc1[MAXN * 64];   // layer1 output (elu'd) -> layer2 input
__device__ float g_h2[MAXN * 128];    // layer2 features [N,8,16]
__device__ float g_as2[MAXN * 8];
__device__ float g_ad2[MAXN * 8];
__device__ float g_w1hi[512 * 64];    // W1 tf32-truncated hi part
__device__ float g_w1lo[512 * 64];    // W1 residual lo part
// CSR scratch
__device__ int g_deg[MAXN];
__device__ int g_off[MAXN];
__device__ int g_cursor[MAXN];
__device__ int g_bsum[128];           // scan block sums (nb = ceil(N/1024) <= 98)
__device__ int g_csr[MAXE];

static inline int cdiv(int a, int b) { return (a + b - 1) / b; }

// Side stream + fork/join events, created once at static init (no device
// memory allocation involved — streams/events are driver objects).
static cudaStream_t g_s1;
static cudaEvent_t g_evFork, g_evJoin;
namespace {
struct StreamInit {
    StreamInit() {
        cudaStreamCreateWithFlags(&g_s1, cudaStreamNonBlocking);
        cudaEventCreateWithFlags(&g_evFork, cudaEventDisableTiming);
        cudaEventCreateWithFlags(&g_evJoin, cudaEventDisableTiming);
    }
} s_streamInit;
}

// ---------------------------------------------------------------------------
// TF32 helpers. hi = rz-truncation to tf32 mantissa (exact, 1 LOP);
// lo = x - hi (exact FSUB). Both passed RAW to mma.tf32 — the HW reads tf32
// operands as fp32-layout registers ignoring the low 13 mantissa bits.
// ---------------------------------------------------------------------------
__device__ __forceinline__ float tf32_trunc(float x) {
    return __uint_as_float(__float_as_uint(x) & 0xFFFFE000u);
}

__device__ __forceinline__ void mma_tf32(float* c, const uint32_t* a, const uint32_t* b) {
    asm volatile(
        "mma.sync.aligned.m16n8k8.row.col.f32.tf32.tf32.f32 "
        "{%0,%1,%2,%3}, {%4,%5,%6,%7}, {%8,%9}, {%0,%1,%2,%3};"
        : "+f"(c[0]), "+f"(c[1]), "+f"(c[2]), "+f"(c[3])
        : "r"(a[0]), "r"(a[1]), "r"(a[2]), "r"(a[3]), "r"(b[0]), "r"(b[1]));
}

// ---------------------------------------------------------------------------
// One-time W1 split: Whi = trunc(W), Wlo = W - Whi. 512*64 = 32768 elems.
// ---------------------------------------------------------------------------
__global__ __launch_bounds__(256) void wsplit_kernel(
    const float* __restrict__ W, float* __restrict__ Whi,
    float* __restrict__ Wlo, int n)
{
    int i = blockIdx.x * blockDim.x + threadIdx.x;
    if (i < n) {
        float w = W[i];
        float hi = tf32_trunc(w);
        Whi[i] = hi;
        Wlo[i] = w - hi;
    }
}

// ---------------------------------------------------------------------------
// GEMM1 (3xTF32): C[N,64] = X[N,512] * W[512,64].
// Tile 128x64, 8 warps (m16 each), K-chunks of 16.
// A staged row-major [row][k], stride 20 words: fragment LDS banks
// (20*gr + gc) mod 32 = {0,20,8,28,16,4,24,12}+{0..3} -> all distinct.
// B (W hi/lo precomputed) staged [k][n], stride 72: banks 8*gc + gr distinct.
// ---------------------------------------------------------------------------
__global__ __launch_bounds__(256) void gemm1_tf32_kernel(
    const float* __restrict__ X, const float* __restrict__ Whi,
    const float* __restrict__ Wlo, float* __restrict__ H, int N)
{
    __shared__ float Ahi[128 * 20];   // [row][k] stride 20
    __shared__ float Alo[128 * 20];
    __shared__ float Bhi[16 * 72];    // [k][n] stride 72
    __shared__ float Blo[16 * 72];

    const int tid = threadIdx.x;
    const int lane = tid & 31;
    const int warp = tid >> 5;          // 0..7
    const int wbase = warp * 16;
    const int rowBase = blockIdx.x * 128;
    const int gr = lane >> 2;           // 0..7
    const int gc = lane & 3;            // 0..3

    float acc[8][4];
#pragma unroll
    for (int i = 0; i < 8; i++)
#pragma unroll
        for (int j = 0; j < 4; j++) acc[i][j] = 0.f;

    for (int k0 = 0; k0 < 512; k0 += 16) {
        // ---- A: 128 rows x 16 k = 512 float4 / 256 thr = 2 each
#pragma unroll
        for (int p = tid; p < 512; p += 256) {
            int r = p >> 2;
            int c4 = (p & 3) << 2;
            int row = rowBase + r;
            float4 v = make_float4(0.f, 0.f, 0.f, 0.f);
            if (row < N) v = *(const float4*)&X[(size_t)row * 512 + k0 + c4];
            float4 hi = make_float4(tf32_trunc(v.x), tf32_trunc(v.y),
                                    tf32_trunc(v.z), tf32_trunc(v.w));
            float4 lo = make_float4(v.x - hi.x, v.y - hi.y,
                                    v.z - hi.z, v.w - hi.w);
            *(float4*)&Ahi[r * 20 + c4] = hi;
            *(float4*)&Alo[r * 20 + c4] = lo;
        }
        // ---- B: 16 k x 64 n = 256 float4, 1 per thread, no conversion
        {
            int k = tid >> 4;
            int c4 = (tid & 15) << 2;
            *(float4*)&Bhi[k * 72 + c4] = *(const float4*)&Whi[(size_t)(k0 + k) * 64 + c4];
            *(float4*)&Blo[k * 72 + c4] = *(const float4*)&Wlo[(size_t)(k0 + k) * 64 + c4];
        }
        __syncthreads();

#pragma unroll
        for (int ks = 0; ks < 2; ks++) {
            int kb = ks * 8 + gc;
            uint32_t ahi[4], alo[4];
            ahi[0] = __float_as_uint(Ahi[(wbase + gr) * 20 + kb]);
            ahi[1] = __float_as_uint(Ahi[(wbase + gr + 8) * 20 + kb]);
            ahi[2] = __float_as_uint(Ahi[(wbase + gr) * 20 + kb + 4]);
            ahi[3] = __float_as_uint(Ahi[(wbase + gr + 8) * 20 + kb + 4]);
            alo[0] = __float_as_uint(Alo[(wbase + gr) * 20 + kb]);
            alo[1] = __float_as_uint(Alo[(wbase + gr + 8) * 20 + kb]);
            alo[2] = __float_as_uint(Alo[(wbase + gr) * 20 + kb + 4]);
            alo[3] = __float_as_uint(Alo[(wbase + gr + 8) * 20 + kb + 4]);
#pragma unroll
            for (int nt = 0; nt < 8; nt++) {
                int nn = nt * 8 + gr;
                uint32_t bhi[2], blo[2];
                bhi[0] = __float_as_uint(Bhi[kb * 72 + nn]);
                bhi[1] = __float_as_uint(Bhi[(kb + 4) * 72 + nn]);
                blo[0] = __float_as_uint(Blo[kb * 72 + nn]);
                blo[1] = __float_as_uint(Blo[(kb + 4) * 72 + nn]);
                mma_tf32(acc[nt], ahi, bhi);
                mma_tf32(acc[nt], ahi, blo);
                mma_tf32(acc[nt], alo, bhi);
            }
        }
        __syncthreads();
    }

    int r0 = rowBase + wbase + gr;
    int r1 = r0 + 8;
#pragma unroll
    for (int nt = 0; nt < 8; nt++) {
        int col = nt * 8 + gc * 2;
        if (r0 < N)
            *(float2*)&H[(size_t)r0 * 64 + col] = make_float2(acc[nt][0], acc[nt][1]);
        if (r1 < N)
            *(float2*)&H[(size_t)r1 * 64 + col] = make_float2(acc[nt][2], acc[nt][3]);
    }
}

// ---------------------------------------------------------------------------
// GEMM2: C[N,128] = X[N,64] * W[64,128], whole-K in smem, A transposed (fp32)
// ---------------------------------------------------------------------------
__global__ __launch_bounds__(256) void gemm2_kernel(
    const float* __restrict__ X, const float* __restrict__ W,
    float* __restrict__ H, int N)
{
    __shared__ float As[64][64];   // [k][row]
    __shared__ float Bs[64][128];  // [k][col]
    const int tid = threadIdx.x;
    const int tx = tid & 15;       // 16 col-groups of 8
    const int ty = tid >> 4;       // 16 row-groups of 4
    const int rowBase = blockIdx.x * 64;

#pragma unroll
    for (int i = tid; i < 2048; i += 256) {
        int r = i >> 5, c4 = (i & 31) << 2;
        *(float4*)&Bs[r][c4] = *(const float4*)&W[(size_t)r * 128 + c4];
    }
#pragma unroll
    for (int i = tid; i < 1024; i += 256) {
        int r = i >> 4, c4 = (i & 15) << 2;
        int row = rowBase + r;
        float4 v = make_float4(0.f, 0.f, 0.f, 0.f);
        if (row < N) v = *(const float4*)&X[(size_t)row * 64 + c4];
        As[c4 + 0][r] = v.x; As[c4 + 1][r] = v.y; As[c4 + 2][r] = v.z; As[c4 + 3][r] = v.w;
    }
    __syncthreads();

    float acc[4][8];
#pragma unroll
    for (int i = 0; i < 4; i++)
#pragma unroll
        for (int j = 0; j < 8; j++) acc[i][j] = 0.f;

#pragma unroll 8
    for (int k = 0; k < 64; k++) {
        float a0 = As[k][ty * 4 + 0];
        float a1 = As[k][ty * 4 + 1];
        float a2 = As[k][ty * 4 + 2];
        float a3 = As[k][ty * 4 + 3];
        float4 b0 = *(float4*)&Bs[k][tx * 8];
        float4 b1 = *(float4*)&Bs[k][tx * 8 + 4];
        acc[0][0] += a0 * b0.x; acc[0][1] += a0 * b0.y; acc[0][2] += a0 * b0.z; acc[0][3] += a0 * b0.w;
        acc[0][4] += a0 * b1.x; acc[0][5] += a0 * b1.y; acc[0][6] += a0 * b1.z; acc[0][7] += a0 * b1.w;
        acc[1][0] += a1 * b0.x; acc[1][1] += a1 * b0.y; acc[1][2] += a1 * b0.z; acc[1][3] += a1 * b0.w;
        acc[1][4] += a1 * b1.x; acc[1][5] += a1 * b1.y; acc[1][6] += a1 * b1.z; acc[1][7] += a1 * b1.w;
        acc[2][0] += a2 * b0.x; acc[2][1] += a2 * b0.y; acc[2][2] += a2 * b0.z; acc[2][3] += a2 * b0.w;
        acc[2][4] += a2 * b1.x; acc[2][5] += a2 * b1.y; acc[2][6] += a2 * b1.z; acc[2][7] += a2 * b1.w;
        acc[3][0] += a3 * b0.x; acc[3][1] += a3 * b0.y; acc[3][2] += a3 * b0.z; acc[3][3] += a3 * b0.w;
        acc[3][4] += a3 * b1.x; acc[3][5] += a3 * b1.y; acc[3][6] += a3 * b1.z; acc[3][7] += a3 * b1.w;
    }
#pragma unroll
    for (int i = 0; i < 4; i++) {
        int row = rowBase + ty * 4 + i;
        if (row < N) {
            *(float4*)&H[(size_t)row * 128 + tx * 8] =
                make_float4(acc[i][0], acc[i][1], acc[i][2], acc[i][3]);
            *(float4*)&H[(size_t)row * 128 + tx * 8 + 4] =
                make_float4(acc[i][4], acc[i][5], acc[i][6], acc[i][7]);
        }
    }
}

// ---------------------------------------------------------------------------
// Per-node attention coefficients: as[n,h] = sum_c h[n,h,c]*a_src[h,c]
// ---------------------------------------------------------------------------
template <int C>
__global__ __launch_bounds__(256) void alpha_kernel(
    const float* __restrict__ H, const float* __restrict__ a_s,
    const float* __restrict__ a_d, float* __restrict__ as_o,
    float* __restrict__ ad_o, int N)
{
    int i = blockIdx.x * blockDim.x + threadIdx.x;
    if (i >= N * 8) return;
    int n = i >> 3, h = i & 7;
    const float* hp = H + (size_t)n * 8 * C + h * C;
    float s = 0.f, d = 0.f;
#pragma unroll
    for (int c = 0; c < C; c++) {
        float v = __ldg(&hp[c]);
        s += v * __ldg(&a_s[h * C + c]);
        d += v * __ldg(&a_d[h * C + c]);
    }
    as_o[i] = s;
    ad_o[i] = d;
}

// ---------------------------------------------------------------------------
// CSR build: histogram -> exclusive scan (3 kernels) -> fill
// ---------------------------------------------------------------------------
__global__ __launch_bounds__(256) void hist_kernel(
    const int* __restrict__ dst, int* __restrict__ deg, int E)
{
    int e = blockIdx.x * blockDim.x + threadIdx.x;
    if (e < E) atomicAdd(&deg[__ldg(&dst[e])], 1);
}

// Block-level exclusive scan: 1024 elems/block (4 per thread), 256 threads.
__global__ __launch_bounds__(256) void scan_partial_kernel(
    const int* __restrict__ deg, int* __restrict__ off,
    int* __restrict__ blockSums, int N)
{
    __shared__ int warpSums[8];
    int tid = threadIdx.x;
    int base = blockIdx.x * 1024 + tid * 4;
    int d0 = base + 0 < N ? deg[base + 0] : 0;
    int d1 = base + 1 < N ? deg[base + 1] : 0;
    int d2 = base + 2 < N ? deg[base + 2] : 0;
    int d3 = base + 3 < N ? deg[base + 3] : 0;
    int s = d0 + d1 + d2 + d3;

    int lane = tid & 31, wid = tid >> 5;
    int v = s;
#pragma unroll
    for (int o = 1; o < 32; o <<= 1) {
        int t = __shfl_up_sync(0xffffffffu, v, o);
        if (lane >= o) v += t;
    }
    if (lane == 31) warpSums[wid] = v;
    __syncthreads();
    if (wid == 0) {
        int w = lane < 8 ? warpSums[lane] : 0;
#pragma unroll
        for (int o = 1; o < 8; o <<= 1) {
            int t = __shfl_up_sync(0xffffffffu, w, o);
            if (lane >= o) w += t;
        }
        if (lane < 8) warpSums[lane] = w;
    }
    __syncthreads();
    int ex = v - s + (wid ? warpSums[wid - 1] : 0);
    if (base + 0 < N) off[base + 0] = ex;
    if (base + 1 < N) off[base + 1] = ex + d0;
    if (base + 2 < N) off[base + 2] = ex + d0 + d1;
    if (base + 3 < N) off[base + 3] = ex + d0 + d1 + d2;
    if (tid == 255) blockSums[blockIdx.x] = warpSums[7];
}

__global__ void scan_sums_kernel(int* __restrict__ blockSums, int nb)
{
    __shared__ int sm[1024];
    int t = threadIdx.x;
    for (int i = t; i < nb; i += blockDim.x) sm[i] = blockSums[i];
    __syncthreads();
    if (t == 0) {
        int run = 0;
        for (int i = 0; i < nb; i++) { int v = sm[i]; sm[i] = run; run += v; }
    }
    __syncthreads();
    for (int i = t; i < nb; i += blockDim.x) blockSums[i] = sm[i];
}

// Reads block sums from a DEDICATED buffer (bsum); writes both off and
// cursor. No aliasing: bsum is never written here.
__global__ __launch_bounds__(256) void scan_add_kernel(
    int* __restrict__ off, const int* __restrict__ bsum,
    int* __restrict__ cursorOut, int N)
{
    int i = blockIdx.x * blockDim.x + threadIdx.x;
    if (i < N) {
        int v = off[i] + __ldg(&bsum[i >> 10]);
        off[i] = v;
        cursorOut[i] = v;
    }
}

__global__ __launch_bounds__(256) void fill_kernel(
    const int* __restrict__ src, const int* __restrict__ dst,
    int* __restrict__ cursor, int* __restrict__ csr, int E)
{
    int e = blockIdx.x * blockDim.x + threadIdx.x;
    if (e >= E) return;
    int d = __ldg(&dst[e]);
    int pos = atomicAdd(&cursor[d], 1);
    csr[pos] = __ldg(&src[e]);
}

// ---------------------------------------------------------------------------
// Layer-1 aggregation (gather): warp per dst node. 64 ch, float2/lane.
// Software-pipelined 2-wide. Fuses softmax norm + bias + ELU. No atomics.
// ---------------------------------------------------------------------------
__global__ __launch_bounds__(256) void agg1_kernel(
    const int* __restrict__ csr, const int* __restrict__ off,
    const int* __restrict__ deg, const float* __restrict__ as,
    const float* __restrict__ ad, const float* __restrict__ H,
    const float* __restrict__ b, float* __restrict__ OUT, int N)
{
    int d = (blockIdx.x * blockDim.x + threadIdx.x) >> 5;
    if (d >= N) return;
    int lane = threadIdx.x & 31;
    int h = lane >> 2;          // 8 heads x 4 lanes, 2 ch per lane
    int c2 = lane * 2;

    float adh = __ldg(&ad[(size_t)d * 8 + h]);

    // self loop
    float ev = __ldg(&as[(size_t)d * 8 + h]) + adh;
    ev = ev > 0.f ? ev : 0.2f * ev;
    float ex = __expf(ev);
    float2 v = __ldg((const float2*)&H[(size_t)d * 64 + c2]);
    float ax = ex * v.x, ay = ex * v.y, den = ex;
    float ax2 = 0.f, ay2 = 0.f, den2 = 0.f;   // second accumulator chain

    int beg = __ldg(&off[d]);
    int cnt = __ldg(&deg[d]);
    int j = 0;
    for (; j + 2 <= cnt; j += 2) {
        int s0 = __ldg(&csr[beg + j]);
        int s1 = __ldg(&csr[beg + j + 1]);
        float e0 = __ldg(&as[(size_t)s0 * 8 + h]);
        float e1 = __ldg(&as[(size_t)s1 * 8 + h]);
        float2 u0 = __ldg((const float2*)&H[(size_t)s0 * 64 + c2]);
        float2 u1 = __ldg((const float2*)&H[(size_t)s1 * 64 + c2]);
        e0 += adh; e0 = e0 > 0.f ? e0 : 0.2f * e0; float x0 = __expf(e0);
        e1 += adh; e1 = e1 > 0.f ? e1 : 0.2f * e1; float x1 = __expf(e1);
        ax  += x0 * u0.x; ay  += x0 * u0.y; den  += x0;
        ax2 += x1 * u1.x; ay2 += x1 * u1.y; den2 += x1;
    }
    if (j < cnt) {
        int s0 = __ldg(&csr[beg + j]);
        float e0 = __ldg(&as[(size_t)s0 * 8 + h]) + adh;
        e0 = e0 > 0.f ? e0 : 0.2f * e0;
        float x0 = __expf(e0);
        float2 u0 = __ldg((const float2*)&H[(size_t)s0 * 64 + c2]);
        ax += x0 * u0.x; ay += x0 * u0.y; den += x0;
    }
    ax += ax2; ay += ay2; den += den2;

    float inv = 1.f / den;
    float o0 = ax * inv + __ldg(&b[c2]);
    float o1 = ay * inv + __ldg(&b[c2 + 1]);
    o0 = o0 > 0.f ? o0 : (__expf(o0) - 1.f);
    o1 = o1 > 0.f ? o1 : (__expf(o1) - 1.f);
    *(float2*)&OUT[(size_t)d * 64 + c2] = make_float2(o0, o1);
}

// ---------------------------------------------------------------------------
// Layer-2 aggregation (gather): warp per dst node. 128 ch, float4/lane.
// Software-pipelined 2-wide. Fuses normalization + head-mean + bias.
// ---------------------------------------------------------------------------
__global__ __launch_bounds__(256) void agg2_kernel(
    const int* __restrict__ csr, const int* __restrict__ off,
    const int* __restrict__ deg, const float* __restrict__ as,
    const float* __restrict__ ad, const float* __restrict__ H,
    const float* __restrict__ b, float* __restrict__ OUT, int N)
{
    int d = (blockIdx.x * blockDim.x + threadIdx.x) >> 5;
    if (d >= N) return;
    int lane = threadIdx.x & 31;
    int h = lane >> 2;          // 8 heads x 4 lanes, 4 ch per lane
    int c4 = lane * 4;

    float adh = __ldg(&ad[(size_t)d * 8 + h]);

    // self loop
    float ev = __ldg(&as[(size_t)d * 8 + h]) + adh;
    ev = ev > 0.f ? ev : 0.2f * ev;
    float ex = __expf(ev);
    float4 v = __ldg((const float4*)&H[(size_t)d * 128 + c4]);
    float a0 = ex * v.x, a1 = ex * v.y, a2 = ex * v.z, a3 = ex * v.w;
    float den = ex;
    float b0a = 0.f, b1a = 0.f, b2a = 0.f, b3a = 0.f, den2 = 0.f;

    int beg = __ldg(&off[d]);
    int cnt = __ldg(&deg[d]);
    int j = 0;
    for (; j + 2 <= cnt; j += 2) {
        int s0 = __ldg(&csr[beg + j]);
        int s1 = __ldg(&csr[beg + j + 1]);
        float e0 = __ldg(&as[(size_t)s0 * 8 + h]);
        float e1 = __ldg(&as[(size_t)s1 * 8 + h]);
        float4 u0 = __ldg((const float4*)&H[(size_t)s0 * 128 + c4]);
        float4 u1 = __ldg((const float4*)&H[(size_t)s1 * 128 + c4]);
        e0 += adh; e0 = e0 > 0.f ? e0 : 0.2f * e0; float x0 = __expf(e0);
        e1 += adh; e1 = e1 > 0.f ? e1 : 0.2f * e1; float x1 = __expf(e1);
        a0  += x0 * u0.x; a1  += x0 * u0.y; a2  += x0 * u0.z; a3  += x0 * u0.w; den  += x0;
        b0a += x1 * u1.x; b1a += x1 * u1.y; b2a += x1 * u1.z; b3a += x1 * u1.w; den2 += x1;
    }
    if (j < cnt) {
        int s0 = __ldg(&csr[beg + j]);
        float e0 = __ldg(&as[(size_t)s0 * 8 + h]) + adh;
        e0 = e0 > 0.f ? e0 : 0.2f * e0;
        float x0 = __expf(e0);
        float4 u0 = __ldg((const float4*)&H[(size_t)s0 * 128 + c4]);
        a0 += x0 * u0.x; a1 += x0 * u0.y; a2 += x0 * u0.z; a3 += x0 * u0.w; den += x0;
    }
    a0 += b0a; a1 += b1a; a2 += b2a; a3 += b3a; den += den2;

    float inv = 1.f / den;
    a0 *= inv; a1 *= inv; a2 *= inv; a3 *= inv;

    // mean over heads: head index = bits [2:4] of lane -> butterfly over 4,8,16
#pragma unroll
    for (int o = 4; o <= 16; o <<= 1) {
        a0 += __shfl_xor_sync(0xffffffffu, a0, o);
        a1 += __shfl_xor_sync(0xffffffffu, a1, o);
        a2 += __shfl_xor_sync(0xffffffffu, a2, o);
        a3 += __shfl_xor_sync(0xffffffffu, a3, o);
    }
    if (lane < 4) {
        int c = lane * 4;
        float4 o4 = make_float4(
            a0 * 0.125f + __ldg(&b[c]),
            a1 * 0.125f + __ldg(&b[c + 1]),
            a2 * 0.125f + __ldg(&b[c + 2]),
            a3 * 0.125f + __ldg(&b[c + 3]));
        *(float4*)&OUT[(size_t)d * 16 + c] = o4;
    }
}

// ---------------------------------------------------------------------------
extern "C" void kernel_launch(void* const* d_in, const int* in_sizes, int n_in,
                              void* d_out, int out_size)
{
    const float* x      = (const float*)d_in[0];
    const int*   ei     = (const int*)  d_in[1];
    const float* W1     = (const float*)d_in[2];
    const float* a_src1 = (const float*)d_in[3];
    const float* a_dst1 = (const float*)d_in[4];
    const float* b1     = (const float*)d_in[5];
    const float* W2     = (const float*)d_in[6];
    const float* a_src2 = (const float*)d_in[7];
    const float* a_dst2 = (const float*)d_in[8];
    const float* b2     = (const float*)d_in[9];

    const int N = in_sizes[0] / 512;
    const int E = in_sizes[1] / 2;
    const int* src = ei;
    const int* dst = ei + E;

    float *h1, *as1, *ad1, *acc1, *h2, *as2, *ad2, *w1hi, *w1lo;
    int *deg, *off, *cursor, *bsum, *csr;
    cudaGetSymbolAddress((void**)&h1,   g_h1);
    cudaGetSymbolAddress((void**)&as1,  g_as1);
    cudaGetSymbolAddress((void**)&ad1,  g_ad1);
    cudaGetSymbolAddress((void**)&acc1, g_acc1);
    cudaGetSymbolAddress((void**)&h2,   g_h2);
    cudaGetSymbolAddress((void**)&as2,  g_as2);
    cudaGetSymbolAddress((void**)&ad2,  g_ad2);
    cudaGetSymbolAddress((void**)&w1hi, g_w1hi);
    cudaGetSymbolAddress((void**)&w1lo, g_w1lo);
    cudaGetSymbolAddress((void**)&deg,    g_deg);
    cudaGetSymbolAddress((void**)&off,    g_off);
    cudaGetSymbolAddress((void**)&cursor, g_cursor);
    cudaGetSymbolAddress((void**)&bsum,   g_bsum);
    cudaGetSymbolAddress((void**)&csr,    g_csr);

    const int nb = cdiv(N, 1024);

    // Submission order is arranged so gemm1_tf32 is the 4th KERNEL launch
    // (profiler window): wsplit(1), hist(2), scan_partial(3), gemm1(4), ...

    // ---- main: W split (gemm1's prerequisite)
    wsplit_kernel<<<cdiv(512 * 64, 256), 256>>>(W1, w1hi, w1lo, 512 * 64);

    // ---- fork CSR build onto side stream
    cudaEventRecord(g_evFork, 0);
    cudaStreamWaitEvent(g_s1, g_evFork, 0);
    cudaMemsetAsync(deg, 0, (size_t)N * sizeof(int), g_s1);
    hist_kernel<<<cdiv(E, 256), 256, 0, g_s1>>>(dst, deg, E);
    scan_partial_kernel<<<nb, 256, 0, g_s1>>>(deg, off, bsum, N);

    // ---- main: layer-1 GEMM (4th kernel launch -> profiled)
    gemm1_tf32_kernel<<<cdiv(N, 128), 256>>>(x, w1hi, w1lo, h1, N);

    // ---- side stream: rest of CSR build
    scan_sums_kernel<<<1, 256, 0, g_s1>>>(bsum, nb);
    scan_add_kernel<<<cdiv(N, 256), 256, 0, g_s1>>>(off, bsum, cursor, N);
    fill_kernel<<<cdiv(E, 256), 256, 0, g_s1>>>(src, dst, cursor, csr, E);
    cudaEventRecord(g_evJoin, g_s1);

    // ---- main: layer 1 continue
    alpha_kernel<8><<<cdiv(N * 8, 256), 256>>>(h1, a_src1, a_dst1, as1, ad1, N);
    cudaStreamWaitEvent(0, g_evJoin, 0);   // join: agg1 needs CSR
    agg1_kernel<<<cdiv(N * 32, 256), 256>>>(csr, off, deg, as1, ad1, h1, b1, acc1, N);

    // ---- Layer 2 ----
    gemm2_kernel<<<cdiv(N, 64), 256>>>(acc1, W2, h2, N);
    alpha_kernel<16><<<cdiv(N * 8, 256), 256>>>(h2, a_src2, a_dst2, as2, ad2, N);
    agg2_kernel<<<cdiv(N * 32, 256), 256>>>(csr, off, deg, as2, ad2, h2, b2, (float*)d_out, N);
}